// round 14
// baseline (speedup 1.0000x reference)
#include <cuda_runtime.h>
#include <cuda_fp16.h>
#include <cstdint>
#include <math.h>

// ---------------------------------------------------------------------------
// GLA layer, GB300 (base sm_103 ISA: mma.sync HMMA path)
// prep (LN + weight splits) -> {q,k,v,a} proj (fp16-split HMMA; 2-pass qkv,
// 3-pass gates; frozen 128x128/256t config, 3-stage cp.async ring) ->
// chunked gated recurrence (float4 smem, MLP-8 scan) -> out proj + residual
// ---------------------------------------------------------------------------
#define B_    4
#define T_    4096
#define DM    1024
#define DI    512
#define H_    8
#define DH    64
#define C_    64
#define NC    (T_ / C_)
#define M_    (B_ * T_)        // 16384
#define BH    (B_ * H_)        // 32
#define NCHUNK (BH * NC)       // 2048
#define SROW  68

// fp32 scratch
__device__ float g_q[M_ * DI];
__device__ float g_k[M_ * DI];
__device__ float g_v[M_ * DI];
__device__ float g_a[M_ * DI];
__device__ float g_o[M_ * DI];
__device__ float g_U[NCHUNK * DH * DH];
__device__ float g_S[NCHUNK * DH * DH];
__device__ float g_D[NCHUNK * DH];
// fp16 hi/lo split operands
__device__ __half g_xnh[M_ * DM], g_xnl[M_ * DM];
__device__ __half g_Wh[1024 * 2048], g_Wl[1024 * 2048];  // [K][Wq|Wk|Wv|Wa]
__device__ __half g_Woh[512 * 1024], g_Wol[512 * 1024];  // [K][N]
__device__ __half g_oh[M_ * DI], g_ol[M_ * DI];

// ---------------------------------------------------------------------------
// PTX helpers
// ---------------------------------------------------------------------------
__device__ __forceinline__ uint32_t smem_u32(const void* p) {
    uint32_t a;
    asm("{ .reg .u64 t; cvta.to.shared.u64 t, %1; cvt.u32.u64 %0, t; }" : "=r"(a) : "l"(p));
    return a;
}
#define CP16(dst, src) asm volatile("cp.async.cg.shared.global [%0], [%1], 16;" :: "r"(dst), "l"(src))
#define CPCOMMIT()     asm volatile("cp.async.commit_group;" ::: "memory")
#define CPWAIT0()      asm volatile("cp.async.wait_group 0;" ::: "memory")
#define CPWAIT1()      asm volatile("cp.async.wait_group 1;" ::: "memory")

#define LDSM4(r, a) asm volatile( \
    "ldmatrix.sync.aligned.m8n8.x4.shared.b16 {%0,%1,%2,%3}, [%4];" \
    : "=r"((r)[0]), "=r"((r)[1]), "=r"((r)[2]), "=r"((r)[3]) : "r"(a))
#define LDSM4T(r, a) asm volatile( \
    "ldmatrix.sync.aligned.m8n8.x4.trans.shared.b16 {%0,%1,%2,%3}, [%4];" \
    : "=r"((r)[0]), "=r"((r)[1]), "=r"((r)[2]), "=r"((r)[3]) : "r"(a))
#define MMA16816(c, a, b0, b1) asm volatile( \
    "mma.sync.aligned.m16n8k16.row.col.f32.f16.f16.f32 " \
    "{%0,%1,%2,%3},{%4,%5,%6,%7},{%8,%9},{%0,%1,%2,%3};" \
    : "+f"((c)[0]), "+f"((c)[1]), "+f"((c)[2]), "+f"((c)[3]) \
    : "r"((a)[0]), "r"((a)[1]), "r"((a)[2]), "r"((a)[3]), "r"(b0), "r"(b1))

// vectorized hi/lo split of 4 floats -> two half2 stores each
__device__ __forceinline__ void split4_store(float f0, float f1, float f2, float f3,
                                             __half* Dh, __half* Dl, size_t o) {
    __half h0 = __float2half_rn(f0), h1 = __float2half_rn(f1);
    __half h2 = __float2half_rn(f2), h3 = __float2half_rn(f3);
    __half2 hp0; hp0.x = h0; hp0.y = h1;
    __half2 hp1; hp1.x = h2; hp1.y = h3;
    *reinterpret_cast<__half2*>(Dh + o)     = hp0;
    *reinterpret_cast<__half2*>(Dh + o + 2) = hp1;
    __half2 lp0, lp1;
    lp0.x = __float2half_rn(f0 - __half2float(h0));
    lp0.y = __float2half_rn(f1 - __half2float(h1));
    lp1.x = __float2half_rn(f2 - __half2float(h2));
    lp1.y = __float2half_rn(f3 - __half2float(h3));
    *reinterpret_cast<__half2*>(Dl + o)     = lp0;
    *reinterpret_cast<__half2*>(Dl + o + 2) = lp1;
}

// ---------------------------------------------------------------------------
// Prep: LN -> fp16 hi/lo (blocks 0..16383) + weight splits (blocks 16384+)
// ---------------------------------------------------------------------------
__global__ void __launch_bounds__(256) prep_kernel(
    const float* __restrict__ x, const float* __restrict__ gamma,
    const float* __restrict__ beta,
    const float* __restrict__ Wq, const float* __restrict__ Wk,
    const float* __restrict__ Wv, const float* __restrict__ Wa,
    const float* __restrict__ Wo)
{
    int bid = blockIdx.x;
    int tid = threadIdx.x;
    if (bid < M_) {
        int row = bid;
        const float4* xr = reinterpret_cast<const float4*>(x + (size_t)row * DM);
        float4 v = xr[tid];
        float s  = v.x + v.y + v.z + v.w;
        float sq = v.x * v.x + v.y * v.y + v.z * v.z + v.w * v.w;
#pragma unroll
        for (int o = 16; o; o >>= 1) {
            s  += __shfl_xor_sync(0xFFFFFFFFu, s, o);
            sq += __shfl_xor_sync(0xFFFFFFFFu, sq, o);
        }
        __shared__ float ss[8], ssq[8];
        int w = tid >> 5, l = tid & 31;
        if (l == 0) { ss[w] = s; ssq[w] = sq; }
        __syncthreads();
        if (tid == 0) {
            float a = 0.f, b = 0.f;
#pragma unroll
            for (int i = 0; i < 8; i++) { a += ss[i]; b += ssq[i]; }
            ss[0] = a; ssq[0] = b;
        }
        __syncthreads();
        float mu   = ss[0] * (1.0f / DM);
        float var  = ssq[0] * (1.0f / DM) - mu * mu;
        float rstd = rsqrtf(var + 1e-5f);
        float4 gg = reinterpret_cast<const float4*>(gamma)[tid];
        float4 bb = reinterpret_cast<const float4*>(beta)[tid];
        float o0 = (v.x - mu) * rstd * gg.x + bb.x;
        float o1 = (v.y - mu) * rstd * gg.y + bb.y;
        float o2 = (v.z - mu) * rstd * gg.z + bb.z;
        float o3 = (v.w - mu) * rstd * gg.w + bb.w;
        size_t base = (size_t)row * DM + tid * 4;
        split4_store(o0, o1, o2, o3, g_xnh, g_xnl, base);
    } else {
        int idx2 = bid - M_;
        int which = idx2 >> 9;          // 0..4
        int blk = idx2 & 511;
        const float* W = (which == 0) ? Wq : (which == 1) ? Wk :
                         (which == 2) ? Wv : (which == 3) ? Wa : Wo;
        int ncols = (which == 4) ? 1024 : 512;
        int ldd   = (which == 4) ? 1024 : 2048;
        int coloff = (which == 4) ? 0 : which * 512;
        __half* Dh = (which == 4) ? g_Woh : g_Wh;
        __half* Dl = (which == 4) ? g_Wol : g_Wl;
        int e = (blk * 256 + tid) * 4;
        int k = e / ncols, n = e % ncols;
        float4 v = *reinterpret_cast<const float4*>(W + e);
        size_t dbase = (size_t)k * ldd + coloff + n;
        split4_store(v.x, v.y, v.z, v.w, Dh, Dl, dbase);
    }
}

// ---------------------------------------------------------------------------
// HMMA GEMM: 128x128 CTA, 8 warps (2x4), warp 64x32, k-stage 32,
// fp16 split: AhBh + AhBl (+ AlBh when third!=0), f32 acc,
// 3-stage cp.async ring (wait_group 1), one sync per stage.
// ---------------------------------------------------------------------------
#define ASTR 40
#define BSTR 136
#define STG_A (128 * ASTR)             // 5120 halves
#define STG_B (32 * BSTR)              // 4352 halves
#define STG_TOT (2 * STG_A + 2 * STG_B)// 18944 halves = 37888 B
#define GEMM_SMEM (3 * STG_TOT * 2)    // 113664 B (2 CTAs/SM still fit)

__device__ __forceinline__ void hmma_prefetch(
    uint32_t base, const __half* Ah, const __half* Al, int lda,
    const __half* Bh, const __half* Bl, int ldb,
    int m0, int n0, int k0, int tid, int third)
{
#pragma unroll
    for (int i = 0; i < 2; i++) {
        int e = tid + i * 256;
        int row = e >> 2, col = (e & 3) * 8;
        size_t ga = (size_t)(m0 + row) * lda + k0 + col;
        CP16(base + (row * ASTR + col) * 2, Ah + ga);
        if (third) CP16(base + (STG_A + row * ASTR + col) * 2, Al + ga);
        int rb = e >> 4, cb = (e & 15) * 8;
        size_t gb = (size_t)(k0 + rb) * ldb + n0 + cb;
        CP16(base + (2 * STG_A + rb * BSTR + cb) * 2, Bh + gb);
        CP16(base + (2 * STG_A + STG_B + rb * BSTR + cb) * 2, Bl + gb);
    }
    CPCOMMIT();
}

__device__ __forceinline__ void hmma_gemm(
    const __half* Ah, const __half* Al, int lda,
    const __half* Bh, const __half* Bl, int ldb,
    int m0, int n0, int K, float c[4][4][4], __half* sm, int third)
{
    int tid = threadIdx.x, lane = tid & 31, wid = tid >> 5;
    int wm = wid >> 2, wn = wid & 3;
    uint32_t smb = smem_u32(sm);
    int stages = K / 32;

    hmma_prefetch(smb,               Ah, Al, lda, Bh, Bl, ldb, m0, n0, 0,  tid, third);
    hmma_prefetch(smb + STG_TOT * 2, Ah, Al, lda, Bh, Bl, ldb, m0, n0, 32, tid, third);

    for (int s = 0; s < stages; s++) {
        if (s + 1 < stages) { CPWAIT1(); } else { CPWAIT0(); }
        __syncthreads();   // readers of buffer (s-1)%3 done; group s landed
        if (s + 2 < stages)
            hmma_prefetch(smb + ((s + 2) % 3) * STG_TOT * 2, Ah, Al, lda, Bh, Bl, ldb,
                          m0, n0, (s + 2) * 32, tid, third);
        uint32_t aH = smb + (s % 3) * STG_TOT * 2;
        uint32_t bH = aH + 2 * STG_A * 2;
#pragma unroll
        for (int ks = 0; ks < 2; ks++) {
            uint32_t ah[4][4], al[4][4];
#pragma unroll
            for (int mi = 0; mi < 4; mi++) {
                uint32_t addr = aH + ((wm * 64 + mi * 16 + (lane & 15)) * ASTR
                                      + ks * 16 + (lane >> 4) * 8) * 2;
                LDSM4(ah[mi], addr);
            }
            if (third) {
#pragma unroll
                for (int mi = 0; mi < 4; mi++) {
                    uint32_t addr = aH + ((wm * 64 + mi * 16 + (lane & 15)) * ASTR
                                          + ks * 16 + (lane >> 4) * 8) * 2;
                    LDSM4(al[mi], addr + STG_A * 2);
                }
            }
            uint32_t bh[2][4], bl[2][4];
#pragma unroll
            for (int np = 0; np < 2; np++) {
                uint32_t addr = bH + ((ks * 16 + (lane & 15)) * BSTR
                                      + wn * 32 + np * 16 + (lane >> 4) * 8) * 2;
                LDSM4T(bh[np], addr);
                LDSM4T(bl[np], addr + STG_B * 2);
            }
            if (third) {
#pragma unroll
                for (int mi = 0; mi < 4; mi++)
#pragma unroll
                    for (int ni = 0; ni < 4; ni++) {
                        int np = ni >> 1, pr = (ni & 1) * 2;
                        MMA16816(c[mi][ni], ah[mi], bh[np][pr], bh[np][pr + 1]);
                        MMA16816(c[mi][ni], ah[mi], bl[np][pr], bl[np][pr + 1]);
                        MMA16816(c[mi][ni], al[mi], bh[np][pr], bh[np][pr + 1]);
                    }
            } else {
#pragma unroll
                for (int mi = 0; mi < 4; mi++)
#pragma unroll
                    for (int ni = 0; ni < 4; ni++) {
                        int np = ni >> 1, pr = (ni & 1) * 2;
                        MMA16816(c[mi][ni], ah[mi], bh[np][pr], bh[np][pr + 1]);
                        MMA16816(c[mi][ni], ah[mi], bl[np][pr], bl[np][pr + 1]);
                    }
            }
        }
        // no bottom sync: next stage's top sync protects buffer reuse
    }
}

__global__ void __launch_bounds__(256) proj_hmma(const float* __restrict__ ba) {
    extern __shared__ __half smh[];
    float c[4][4][4];
#pragma unroll
    for (int i = 0; i < 4; i++)
#pragma unroll
        for (int j = 0; j < 4; j++)
#pragma unroll
            for (int q = 0; q < 4; q++) c[i][j][q] = 0.f;
    int n0 = blockIdx.x * 128, m0 = blockIdx.y * 128;
    int which = n0 >> 9, cb = n0 & 511;
    int third = (which == 3);
    hmma_gemm(g_xnh, g_xnl, DM, g_Wh, g_Wl, 2048, m0, n0, DM, c, smh, third);

    int tid = threadIdx.x, lane = tid & 31, wid = tid >> 5;
    int wm = wid >> 2, wn = wid & 3;
    float* dst = (which == 0) ? g_q : (which == 1) ? g_k : (which == 2) ? g_v : g_a;
#pragma unroll
    for (int mi = 0; mi < 4; mi++) {
        int row = m0 + wm * 64 + mi * 16 + (lane >> 2);
#pragma unroll
        for (int ni = 0; ni < 4; ni++) {
            int col = cb + wn * 32 + ni * 8 + (lane & 3) * 2;
            float v0 = c[mi][ni][0], v1 = c[mi][ni][1];
            float v2 = c[mi][ni][2], v3 = c[mi][ni][3];
            if (third) {
                float b0 = ba[col], b1 = ba[col + 1];
                v0 = 1.0f / (1.0f + expf(-(v0 + b0)));
                v1 = 1.0f / (1.0f + expf(-(v1 + b1)));
                v2 = 1.0f / (1.0f + expf(-(v2 + b0)));
                v3 = 1.0f / (1.0f + expf(-(v3 + b1)));
            }
            *reinterpret_cast<float2*>(dst + (size_t)row * DI + col) = make_float2(v0, v1);
            *reinterpret_cast<float2*>(dst + (size_t)(row + 8) * DI + col) = make_float2(v2, v3);
        }
    }
}

__global__ void __launch_bounds__(256) out_hmma(const float* __restrict__ x,
                                                float* __restrict__ out) {
    extern __shared__ __half smh[];
    float c[4][4][4];
#pragma unroll
    for (int i = 0; i < 4; i++)
#pragma unroll
        for (int j = 0; j < 4; j++)
#pragma unroll
            for (int q = 0; q < 4; q++) c[i][j][q] = 0.f;
    int n0 = blockIdx.x * 128, m0 = blockIdx.y * 128;
    hmma_gemm(g_oh, g_ol, DI, g_Woh, g_Wol, DM, m0, n0, DI, c, smh, 0);

    int tid = threadIdx.x, lane = tid & 31, wid = tid >> 5;
    int wm = wid >> 2, wn = wid & 3;
#pragma unroll
    for (int mi = 0; mi < 4; mi++) {
        int row = m0 + wm * 64 + mi * 16 + (lane >> 2);
#pragma unroll
        for (int ni = 0; ni < 4; ni++) {
            int col = n0 + wn * 32 + ni * 8 + (lane & 3) * 2;
            float2 x0 = *reinterpret_cast<const float2*>(x + (size_t)row * DM + col);
            float2 x1 = *reinterpret_cast<const float2*>(x + (size_t)(row + 8) * DM + col);
            *reinterpret_cast<float2*>(out + (size_t)row * DM + col) =
                make_float2(c[mi][ni][0] + x0.x, c[mi][ni][1] + x0.y);
            *reinterpret_cast<float2*>(out + (size_t)(row + 8) * DM + col) =
                make_float2(c[mi][ni][2] + x1.x, c[mi][ni][3] + x1.y);
        }
    }
}

// ---------------------------------------------------------------------------
// Pass A: per (b,h,chunk). G cumprod, q~=G*q, k~=knorm/G, D, U=K~^T V,
// O_intra = ((Q~K~^T).mask) V.  float4-vectorized reductions.
// ---------------------------------------------------------------------------
extern __shared__ float smemA[];
__global__ void __launch_bounds__(256) rec_intra() {
    float* sA = smemA;
    float* sQ = sA + 64 * SROW;
    float* sK = sQ + 64 * SROW;
    float* sV = sK + 64 * SROW;

    int idx = blockIdx.x;
    int c = idx % NC, bh = idx / NC;
    int b = bh / H_, h = bh % H_;
    int m0 = b * T_ + c * C_;
    int col = h * DH;
    int tid = threadIdx.x;

#pragma unroll
    for (int r = 0; r < 4; r++) {
        int e = tid + r * 256;
        int t = e >> 4; int d4 = (e & 15) * 4;
        float4 va = *reinterpret_cast<const float4*>(&g_a[(size_t)(m0 + t) * DI + col + d4]);
        *reinterpret_cast<float4*>(&sA[t * SROW + d4]) = va;
    }
    __syncthreads();
    if (tid < 64) {
        float g = 1.0f;
        for (int t = 0; t < 64; t++) { g *= sA[t * SROW + tid]; sA[t * SROW + tid] = g; }
    }
    __syncthreads();
#pragma unroll
    for (int r = 0; r < 4; r++) {
        int e = tid + r * 256;
        int t = e >> 4; int d4 = (e & 15) * 4;
        float4 vq = *reinterpret_cast<const float4*>(&g_q[(size_t)(m0 + t) * DI + col + d4]);
        float4 gg = *reinterpret_cast<const float4*>(&sA[t * SROW + d4]);
        vq.x *= gg.x; vq.y *= gg.y; vq.z *= gg.z; vq.w *= gg.w;
        *reinterpret_cast<float4*>(&sQ[t * SROW + d4]) = vq;
        *reinterpret_cast<float4*>(&g_q[(size_t)(m0 + t) * DI + col + d4]) = vq;
    }
    {
        int w = tid >> 5, l = tid & 31;
#pragma unroll
        for (int rr = 0; rr < 8; rr++) {
            int t = w * 8 + rr;
            float x0 = g_k[(size_t)(m0 + t) * DI + col + l];
            float x1 = g_k[(size_t)(m0 + t) * DI + col + l + 32];
            float s = x0 * x0 + x1 * x1;
#pragma unroll
            for (int o = 16; o; o >>= 1) s += __shfl_xor_sync(0xFFFFFFFFu, s, o);
            float inv = 1.0f / fmaxf(sqrtf(s), 1e-12f);
            sK[t * SROW + l]      = x0 * inv / sA[t * SROW + l];
            sK[t * SROW + l + 32] = x1 * inv / sA[t * SROW + l + 32];
        }
    }
#pragma unroll
    for (int r = 0; r < 4; r++) {
        int e = tid + r * 256;
        int t = e >> 4; int d4 = (e & 15) * 4;
        float4 vv = *reinterpret_cast<const float4*>(&g_v[(size_t)(m0 + t) * DI + col + d4]);
        *reinterpret_cast<float4*>(&sV[t * SROW + d4]) = vv;
    }
    if (tid < 64) g_D[(size_t)idx * 64 + tid] = sA[63 * SROW + tid];
    __syncthreads();

    int ty = tid >> 4, tx = tid & 15;
    int r0 = ty * 4, c0 = tx * 4;
    // U[j][i] = sum_s K~[s][j] V[s][i]
    {
        float acc[4][4];
#pragma unroll
        for (int a = 0; a < 4; a++)
#pragma unroll
            for (int bb2 = 0; bb2 < 4; bb2++) acc[a][bb2] = 0.f;
        for (int s = 0; s < 64; s++) {
            float4 kk = *reinterpret_cast<const float4*>(&sK[s * SROW + r0]);
            float4 vv = *reinterpret_cast<const float4*>(&sV[s * SROW + c0]);
            float ka[4] = {kk.x, kk.y, kk.z, kk.w};
            float vb[4] = {vv.x, vv.y, vv.z, vv.w};
#pragma unroll
            for (int a = 0; a < 4; a++)
#pragma unroll
                for (int bb2 = 0; bb2 < 4; bb2++) acc[a][bb2] += ka[a] * vb[bb2];
        }
#pragma unroll
        for (int a = 0; a < 4; a++) {
            float4 o4 = make_float4(acc[a][0], acc[a][1], acc[a][2], acc[a][3]);
            *reinterpret_cast<float4*>(&g_U[(size_t)idx * 4096 + (r0 + a) * 64 + c0]) = o4;
        }
    }
    // P[t][s] = sum_j Q~[t][j] K~[s][j] (float4 over j)
    {
        float acc[4][4];
#pragma unroll
        for (int a = 0; a < 4; a++)
#pragma unroll
            for (int bb2 = 0; bb2 < 4; bb2++) acc[a][bb2] = 0.f;
        for (int j = 0; j < 64; j += 4) {
            float4 qa4[4], kb4[4];
#pragma unroll
            for (int a = 0; a < 4; a++)
                qa4[a] = *reinterpret_cast<const float4*>(&sQ[(r0 + a) * SROW + j]);
#pragma unroll
            for (int bb2 = 0; bb2 < 4; bb2++)
                kb4[bb2] = *reinterpret_cast<const float4*>(&sK[(c0 + bb2) * SROW + j]);
#pragma unroll
            for (int a = 0; a < 4; a++)
#pragma unroll
                for (int bb2 = 0; bb2 < 4; bb2++) {
                    acc[a][bb2] += qa4[a].x * kb4[bb2].x;
                    acc[a][bb2] += qa4[a].y * kb4[bb2].y;
                    acc[a][bb2] += qa4[a].z * kb4[bb2].z;
                    acc[a][bb2] += qa4[a].w * kb4[bb2].w;
                }
        }
#pragma unroll
        for (int a = 0; a < 4; a++) {
#pragma unroll
            for (int bb2 = 0; bb2 < 4; bb2++)
                if (c0 + bb2 > r0 + a) acc[a][bb2] = 0.f;
            float4 o4 = make_float4(acc[a][0], acc[a][1], acc[a][2], acc[a][3]);
            *reinterpret_cast<float4*>(&sA[(r0 + a) * SROW + c0]) = o4;
        }
    }
    __syncthreads();
    // O_intra[t][i] = sum_s P[t][s] V[s][i] (float4 over s for P)
    {
        float acc[4][4];
#pragma unroll
        for (int a = 0; a < 4; a++)
#pragma unroll
            for (int bb2 = 0; bb2 < 4; bb2++) acc[a][bb2] = 0.f;
        for (int s = 0; s < 64; s += 4) {
            float4 pa4[4], vb4[4];
#pragma unroll
            for (int a = 0; a < 4; a++)
                pa4[a] = *reinterpret_cast<const float4*>(&sA[(r0 + a) * SROW + s]);
#pragma unroll
            for (int si = 0; si < 4; si++)
                vb4[si] = *reinterpret_cast<const float4*>(&sV[(s + si) * SROW + c0]);
#pragma unroll
            for (int a = 0; a < 4; a++) {
                acc[a][0] += pa4[a].x * vb4[0].x; acc[a][1] += pa4[a].x * vb4[0].y;
                acc[a][2] += pa4[a].x * vb4[0].z; acc[a][3] += pa4[a].x * vb4[0].w;
                acc[a][0] += pa4[a].y * vb4[1].x; acc[a][1] += pa4[a].y * vb4[1].y;
                acc[a][2] += pa4[a].y * vb4[1].z; acc[a][3] += pa4[a].y * vb4[1].w;
                acc[a][0] += pa4[a].z * vb4[2].x; acc[a][1] += pa4[a].z * vb4[2].y;
                acc[a][2] += pa4[a].z * vb4[2].z; acc[a][3] += pa4[a].z * vb4[2].w;
                acc[a][0] += pa4[a].w * vb4[3].x; acc[a][1] += pa4[a].w * vb4[3].y;
                acc[a][2] += pa4[a].w * vb4[3].z; acc[a][3] += pa4[a].w * vb4[3].w;
            }
        }
#pragma unroll
        for (int a = 0; a < 4; a++) {
            float4 o4 = make_float4(acc[a][0], acc[a][1], acc[a][2], acc[a][3]);
            *reinterpret_cast<float4*>(&g_o[(size_t)(m0 + r0 + a) * DI + col + c0]) = o4;
        }
    }
}

// ---------------------------------------------------------------------------
// Pass B: scan over chunks. grid (32, 8), 256 thr; float2/thread, MLP-8
// register ring prefetch.
// ---------------------------------------------------------------------------
__global__ void __launch_bounds__(256) rec_state() {
    int bh = blockIdx.x;
    int seg = blockIdx.y;
    int tid = threadIdx.x;
    int idx = seg * 512 + tid * 2;
    int j = idx >> 6;
    size_t base0 = (size_t)(bh * NC) * 4096 + idx;
    size_t dbase = (size_t)(bh * NC) * 64 + j;
    float2 S = make_float2(0.f, 0.f);
    float2 ub[8];
    float db[8];
#pragma unroll
    for (int i = 0; i < 8; i++) {
        ub[i] = *reinterpret_cast<const float2*>(&g_U[base0 + (size_t)i * 4096]);
        db[i] = g_D[dbase + (size_t)i * 64];
    }
    for (int c = 0; c < NC; c += 8) {
#pragma unroll
        for (int q = 0; q < 8; q++) {
            int cc = c + q;
            *reinterpret_cast<float2*>(&g_S[base0 + (size_t)cc * 4096]) = S;
            float2 uc = ub[q];
            float dc = db[q];
            if (cc + 8 < NC) {
                ub[q] = *reinterpret_cast<const float2*>(&g_U[base0 + (size_t)(cc + 8) * 4096]);
                db[q] = g_D[dbase + (size_t)(cc + 8) * 64];
            }
            S.x = dc * (S.x + uc.x);
            S.y = dc * (S.y + uc.y);
        }
    }
}

// ---------------------------------------------------------------------------
// Pass C: O = g_o (intra) + q~ @ S_in, written as fp16 hi/lo.
// ---------------------------------------------------------------------------
__global__ void __launch_bounds__(256) rec_inter() {
    __shared__ float sQ[64 * SROW];
    __shared__ float sS[64 * SROW];
    int idx = blockIdx.x;
    int c = idx % NC, bh = idx / NC;
    int b = bh / H_, h = bh % H_;
    int m0 = b * T_ + c * C_;
    int col = h * DH;
    int tid = threadIdx.x;
#pragma unroll
    for (int r = 0; r < 4; r++) {
        int e = tid + r * 256;
        int t = e >> 4; int d4 = (e & 15) * 4;
        *reinterpret_cast<float4*>(&sQ[t * SROW + d4]) =
            *reinterpret_cast<const float4*>(&g_q[(size_t)(m0 + t) * DI + col + d4]);
        *reinterpret_cast<float4*>(&sS[t * SROW + d4]) =
            *reinterpret_cast<const float4*>(&g_S[(size_t)idx * 4096 + t * 64 + d4]);
    }
    __syncthreads();
    int ty = tid >> 4, tx = tid & 15;
    int r0 = ty * 4, c0 = tx * 4;
    float acc[4][4];
#pragma unroll
    for (int a = 0; a < 4; a++)
#pragma unroll
        for (int bb2 = 0; bb2 < 4; bb2++) acc[a][bb2] = 0.f;
    for (int j = 0; j < 64; j += 4) {
        float4 qa4[4], sv4[4];
#pragma unroll
        for (int a = 0; a < 4; a++)
            qa4[a] = *reinterpret_cast<const float4*>(&sQ[(r0 + a) * SROW + j]);
#pragma unroll
        for (int ji = 0; ji < 4; ji++)
            sv4[ji] = *reinterpret_cast<const float4*>(&sS[(j + ji) * SROW + c0]);
#pragma unroll
        for (int a = 0; a < 4; a++) {
            acc[a][0] += qa4[a].x * sv4[0].x; acc[a][1] += qa4[a].x * sv4[0].y;
            acc[a][2] += qa4[a].x * sv4[0].z; acc[a][3] += qa4[a].x * sv4[0].w;
            acc[a][0] += qa4[a].y * sv4[1].x; acc[a][1] += qa4[a].y * sv4[1].y;
            acc[a][2] += qa4[a].y * sv4[1].z; acc[a][3] += qa4[a].y * sv4[1].w;
            acc[a][0] += qa4[a].z * sv4[2].x; acc[a][1] += qa4[a].z * sv4[2].y;
            acc[a][2] += qa4[a].z * sv4[2].z; acc[a][3] += qa4[a].z * sv4[2].w;
            acc[a][0] += qa4[a].w * sv4[3].x; acc[a][1] += qa4[a].w * sv4[3].y;
            acc[a][2] += qa4[a].w * sv4[3].z; acc[a][3] += qa4[a].w * sv4[3].w;
        }
    }
#pragma unroll
    for (int a = 0; a < 4; a++) {
        size_t off = (size_t)(m0 + r0 + a) * DI + col + c0;
        float4 cur = *reinterpret_cast<const float4*>(&g_o[off]);
        split4_store(cur.x + acc[a][0], cur.y + acc[a][1],
                     cur.z + acc[a][2], cur.w + acc[a][3], g_oh, g_ol, off);
    }
}

// ---------------------------------------------------------------------------
extern "C" void kernel_launch(void* const* d_in, const int* in_sizes, int n_in,
                              void* d_out, int out_size) {
    const float* x     = (const float*)d_in[0];
    const float* Wq    = (const float*)d_in[1];
    const float* Wk    = (const float*)d_in[2];
    const float* Wv    = (const float*)d_in[3];
    const float* Wa    = (const float*)d_in[4];
    const float* ba    = (const float*)d_in[5];
    const float* Wo    = (const float*)d_in[6];
    const float* gamma = (const float*)d_in[7];
    const float* beta  = (const float*)d_in[8];
    float* out = (float*)d_out;

    const int smemA = 4 * 64 * SROW * sizeof(float);
    cudaFuncSetAttribute(rec_intra, cudaFuncAttributeMaxDynamicSharedMemorySize, smemA);
    cudaFuncSetAttribute(proj_hmma, cudaFuncAttributeMaxDynamicSharedMemorySize, GEMM_SMEM);
    cudaFuncSetAttribute(out_hmma, cudaFuncAttributeMaxDynamicSharedMemorySize, GEMM_SMEM);

    prep_kernel<<<M_ + 5 * 512, 256>>>(x, gamma, beta, Wq, Wk, Wv, Wa, Wo);
    proj_hmma<<<dim3(16, 128), 256, GEMM_SMEM>>>(ba);
    rec_intra<<<NCHUNK, 256, smemA>>>();
    rec_state<<<dim3(32, 8), 256>>>();
    rec_inter<<<NCHUNK, 256>>>();
    out_hmma<<<dim3(8, 128), 256, GEMM_SMEM>>>(x, out);
}

// round 15
// speedup vs baseline: 1.0128x; 1.0128x over previous
#include <cuda_runtime.h>
#include <cuda_fp16.h>
#include <cstdint>
#include <math.h>

// ---------------------------------------------------------------------------
// GLA layer, GB300 (base sm_103 ISA: mma.sync HMMA path)
// prep (LN + weight splits) -> {q,k,v,a} proj (fp16-split HMMA; 2-pass qkv,
// 3-pass gates; frozen 128x128/256t config, 2-stage dbl buffer, single-sync
// stages) -> chunked gated recurrence (float4 smem, MLP-8 scan) ->
// out proj + residual
// ---------------------------------------------------------------------------
#define B_    4
#define T_    4096
#define DM    1024
#define DI    512
#define H_    8
#define DH    64
#define C_    64
#define NC    (T_ / C_)
#define M_    (B_ * T_)        // 16384
#define BH    (B_ * H_)        // 32
#define NCHUNK (BH * NC)       // 2048
#define SROW  68

// fp32 scratch
__device__ float g_q[M_ * DI];
__device__ float g_k[M_ * DI];
__device__ float g_v[M_ * DI];
__device__ float g_a[M_ * DI];
__device__ float g_o[M_ * DI];
__device__ float g_U[NCHUNK * DH * DH];
__device__ float g_S[NCHUNK * DH * DH];
__device__ float g_D[NCHUNK * DH];
// fp16 hi/lo split operands
__device__ __half g_xnh[M_ * DM], g_xnl[M_ * DM];
__device__ __half g_Wh[1024 * 2048], g_Wl[1024 * 2048];  // [K][Wq|Wk|Wv|Wa]
__device__ __half g_Woh[512 * 1024], g_Wol[512 * 1024];  // [K][N]
__device__ __half g_oh[M_ * DI], g_ol[M_ * DI];

// ---------------------------------------------------------------------------
// PTX helpers
// ---------------------------------------------------------------------------
__device__ __forceinline__ uint32_t smem_u32(const void* p) {
    uint32_t a;
    asm("{ .reg .u64 t; cvta.to.shared.u64 t, %1; cvt.u32.u64 %0, t; }" : "=r"(a) : "l"(p));
    return a;
}
#define CP16(dst, src) asm volatile("cp.async.cg.shared.global [%0], [%1], 16;" :: "r"(dst), "l"(src))
#define CPCOMMIT()     asm volatile("cp.async.commit_group;" ::: "memory")
#define CPWAIT0()      asm volatile("cp.async.wait_group 0;" ::: "memory")

#define LDSM4(r, a) asm volatile( \
    "ldmatrix.sync.aligned.m8n8.x4.shared.b16 {%0,%1,%2,%3}, [%4];" \
    : "=r"((r)[0]), "=r"((r)[1]), "=r"((r)[2]), "=r"((r)[3]) : "r"(a))
#define LDSM4T(r, a) asm volatile( \
    "ldmatrix.sync.aligned.m8n8.x4.trans.shared.b16 {%0,%1,%2,%3}, [%4];" \
    : "=r"((r)[0]), "=r"((r)[1]), "=r"((r)[2]), "=r"((r)[3]) : "r"(a))
#define MMA16816(c, a, b0, b1) asm volatile( \
    "mma.sync.aligned.m16n8k16.row.col.f32.f16.f16.f32 " \
    "{%0,%1,%2,%3},{%4,%5,%6,%7},{%8,%9},{%0,%1,%2,%3};" \
    : "+f"((c)[0]), "+f"((c)[1]), "+f"((c)[2]), "+f"((c)[3]) \
    : "r"((a)[0]), "r"((a)[1]), "r"((a)[2]), "r"((a)[3]), "r"(b0), "r"(b1))

// vectorized hi/lo split of 4 floats -> two half2 stores each
__device__ __forceinline__ void split4_store(float f0, float f1, float f2, float f3,
                                             __half* Dh, __half* Dl, size_t o) {
    __half h0 = __float2half_rn(f0), h1 = __float2half_rn(f1);
    __half h2 = __float2half_rn(f2), h3 = __float2half_rn(f3);
    __half2 hp0; hp0.x = h0; hp0.y = h1;
    __half2 hp1; hp1.x = h2; hp1.y = h3;
    *reinterpret_cast<__half2*>(Dh + o)     = hp0;
    *reinterpret_cast<__half2*>(Dh + o + 2) = hp1;
    __half2 lp0, lp1;
    lp0.x = __float2half_rn(f0 - __half2float(h0));
    lp0.y = __float2half_rn(f1 - __half2float(h1));
    lp1.x = __float2half_rn(f2 - __half2float(h2));
    lp1.y = __float2half_rn(f3 - __half2float(h3));
    *reinterpret_cast<__half2*>(Dl + o)     = lp0;
    *reinterpret_cast<__half2*>(Dl + o + 2) = lp1;
}

// ---------------------------------------------------------------------------
// Prep: LN -> fp16 hi/lo (blocks 0..16383) + weight splits (blocks 16384+)
// ---------------------------------------------------------------------------
__global__ void __launch_bounds__(256) prep_kernel(
    const float* __restrict__ x, const float* __restrict__ gamma,
    const float* __restrict__ beta,
    const float* __restrict__ Wq, const float* __restrict__ Wk,
    const float* __restrict__ Wv, const float* __restrict__ Wa,
    const float* __restrict__ Wo)
{
    int bid = blockIdx.x;
    int tid = threadIdx.x;
    if (bid < M_) {
        int row = bid;
        const float4* xr = reinterpret_cast<const float4*>(x + (size_t)row * DM);
        float4 v = xr[tid];
        float s  = v.x + v.y + v.z + v.w;
        float sq = v.x * v.x + v.y * v.y + v.z * v.z + v.w * v.w;
#pragma unroll
        for (int o = 16; o; o >>= 1) {
            s  += __shfl_xor_sync(0xFFFFFFFFu, s, o);
            sq += __shfl_xor_sync(0xFFFFFFFFu, sq, o);
        }
        __shared__ float ss[8], ssq[8];
        int w = tid >> 5, l = tid & 31;
        if (l == 0) { ss[w] = s; ssq[w] = sq; }
        __syncthreads();
        if (tid == 0) {
            float a = 0.f, b = 0.f;
#pragma unroll
            for (int i = 0; i < 8; i++) { a += ss[i]; b += ssq[i]; }
            ss[0] = a; ssq[0] = b;
        }
        __syncthreads();
        float mu   = ss[0] * (1.0f / DM);
        float var  = ssq[0] * (1.0f / DM) - mu * mu;
        float rstd = rsqrtf(var + 1e-5f);
        float4 gg = reinterpret_cast<const float4*>(gamma)[tid];
        float4 bb = reinterpret_cast<const float4*>(beta)[tid];
        float o0 = (v.x - mu) * rstd * gg.x + bb.x;
        float o1 = (v.y - mu) * rstd * gg.y + bb.y;
        float o2 = (v.z - mu) * rstd * gg.z + bb.z;
        float o3 = (v.w - mu) * rstd * gg.w + bb.w;
        size_t base = (size_t)row * DM + tid * 4;
        split4_store(o0, o1, o2, o3, g_xnh, g_xnl, base);
    } else {
        int idx2 = bid - M_;
        int which = idx2 >> 9;          // 0..4
        int blk = idx2 & 511;
        const float* W = (which == 0) ? Wq : (which == 1) ? Wk :
                         (which == 2) ? Wv : (which == 3) ? Wa : Wo;
        int ncols = (which == 4) ? 1024 : 512;
        int ldd   = (which == 4) ? 1024 : 2048;
        int coloff = (which == 4) ? 0 : which * 512;
        __half* Dh = (which == 4) ? g_Woh : g_Wh;
        __half* Dl = (which == 4) ? g_Wol : g_Wl;
        int e = (blk * 256 + tid) * 4;
        int k = e / ncols, n = e % ncols;
        float4 v = *reinterpret_cast<const float4*>(W + e);
        size_t dbase = (size_t)k * ldd + coloff + n;
        split4_store(v.x, v.y, v.z, v.w, Dh, Dl, dbase);
    }
}

// ---------------------------------------------------------------------------
// HMMA GEMM: 128x128 CTA, 8 warps (2x4), warp 64x32, k-stage 32,
// fp16 split: AhBh + AhBl (+ AlBh when third!=0), f32 acc, cp.async dbl
// buffer, ONE sync per stage. (R13 configuration — FROZEN)
// ---------------------------------------------------------------------------
#define ASTR 40
#define BSTR 136
#define STG_A (128 * ASTR)             // 5120 halves
#define STG_B (32 * BSTR)              // 4352 halves
#define STG_TOT (2 * STG_A + 2 * STG_B)// 18944 halves = 37888 B
#define GEMM_SMEM (2 * STG_TOT * 2)    // 75776 B (2 CTAs/SM)

__device__ __forceinline__ void hmma_prefetch(
    uint32_t base, const __half* Ah, const __half* Al, int lda,
    const __half* Bh, const __half* Bl, int ldb,
    int m0, int n0, int k0, int tid, int third)
{
#pragma unroll
    for (int i = 0; i < 2; i++) {
        int e = tid + i * 256;
        int row = e >> 2, col = (e & 3) * 8;
        size_t ga = (size_t)(m0 + row) * lda + k0 + col;
        CP16(base + (row * ASTR + col) * 2, Ah + ga);
        if (third) CP16(base + (STG_A + row * ASTR + col) * 2, Al + ga);
        int rb = e >> 4, cb = (e & 15) * 8;
        size_t gb = (size_t)(k0 + rb) * ldb + n0 + cb;
        CP16(base + (2 * STG_A + rb * BSTR + cb) * 2, Bh + gb);
        CP16(base + (2 * STG_A + STG_B + rb * BSTR + cb) * 2, Bl + gb);
    }
    CPCOMMIT();
}

__device__ __forceinline__ void hmma_gemm(
    const __half* Ah, const __half* Al, int lda,
    const __half* Bh, const __half* Bl, int ldb,
    int m0, int n0, int K, float c[4][4][4], __half* sm, int third)
{
    int tid = threadIdx.x, lane = tid & 31, wid = tid >> 5;
    int wm = wid >> 2, wn = wid & 3;
    uint32_t smb = smem_u32(sm);
    int stages = K / 32;

    hmma_prefetch(smb, Ah, Al, lda, Bh, Bl, ldb, m0, n0, 0, tid, third);

    for (int s = 0; s < stages; s++) {
        int buf = s & 1;
        CPWAIT0();
        __syncthreads();   // all threads done with buf^1 reads AND prefetch landed
        if (s + 1 < stages)
            hmma_prefetch(smb + (buf ^ 1) * STG_TOT * 2, Ah, Al, lda, Bh, Bl, ldb,
                          m0, n0, (s + 1) * 32, tid, third);
        uint32_t aH = smb + buf * STG_TOT * 2;
        uint32_t bH = aH + 2 * STG_A * 2;
#pragma unroll
        for (int ks = 0; ks < 2; ks++) {
            uint32_t ah[4][4], al[4][4];
#pragma unroll
            for (int mi = 0; mi < 4; mi++) {
                uint32_t addr = aH + ((wm * 64 + mi * 16 + (lane & 15)) * ASTR
                                      + ks * 16 + (lane >> 4) * 8) * 2;
                LDSM4(ah[mi], addr);
            }
            if (third) {
#pragma unroll
                for (int mi = 0; mi < 4; mi++) {
                    uint32_t addr = aH + ((wm * 64 + mi * 16 + (lane & 15)) * ASTR
                                          + ks * 16 + (lane >> 4) * 8) * 2;
                    LDSM4(al[mi], addr + STG_A * 2);
                }
            }
            uint32_t bh[2][4], bl[2][4];
#pragma unroll
            for (int np = 0; np < 2; np++) {
                uint32_t addr = bH + ((ks * 16 + (lane & 15)) * BSTR
                                      + wn * 32 + np * 16 + (lane >> 4) * 8) * 2;
                LDSM4T(bh[np], addr);
                LDSM4T(bl[np], addr + STG_B * 2);
            }
            if (third) {
#pragma unroll
                for (int mi = 0; mi < 4; mi++)
#pragma unroll
                    for (int ni = 0; ni < 4; ni++) {
                        int np = ni >> 1, pr = (ni & 1) * 2;
                        MMA16816(c[mi][ni], ah[mi], bh[np][pr], bh[np][pr + 1]);
                        MMA16816(c[mi][ni], ah[mi], bl[np][pr], bl[np][pr + 1]);
                        MMA16816(c[mi][ni], al[mi], bh[np][pr], bh[np][pr + 1]);
                    }
            } else {
#pragma unroll
                for (int mi = 0; mi < 4; mi++)
#pragma unroll
                    for (int ni = 0; ni < 4; ni++) {
                        int np = ni >> 1, pr = (ni & 1) * 2;
                        MMA16816(c[mi][ni], ah[mi], bh[np][pr], bh[np][pr + 1]);
                        MMA16816(c[mi][ni], ah[mi], bl[np][pr], bl[np][pr + 1]);
                    }
            }
        }
        // no bottom sync: next stage's top sync protects buffer reuse
    }
}

__global__ void __launch_bounds__(256) proj_hmma(const float* __restrict__ ba) {
    extern __shared__ __half smh[];
    float c[4][4][4];
#pragma unroll
    for (int i = 0; i < 4; i++)
#pragma unroll
        for (int j = 0; j < 4; j++)
#pragma unroll
            for (int q = 0; q < 4; q++) c[i][j][q] = 0.f;
    int n0 = blockIdx.x * 128, m0 = blockIdx.y * 128;
    int which = n0 >> 9, cb = n0 & 511;
    int third = (which == 3);
    hmma_gemm(g_xnh, g_xnl, DM, g_Wh, g_Wl, 2048, m0, n0, DM, c, smh, third);

    int tid = threadIdx.x, lane = tid & 31, wid = tid >> 5;
    int wm = wid >> 2, wn = wid & 3;
    float* dst = (which == 0) ? g_q : (which == 1) ? g_k : (which == 2) ? g_v : g_a;
#pragma unroll
    for (int mi = 0; mi < 4; mi++) {
        int row = m0 + wm * 64 + mi * 16 + (lane >> 2);
#pragma unroll
        for (int ni = 0; ni < 4; ni++) {
            int col = cb + wn * 32 + ni * 8 + (lane & 3) * 2;
            float v0 = c[mi][ni][0], v1 = c[mi][ni][1];
            float v2 = c[mi][ni][2], v3 = c[mi][ni][3];
            if (third) {
                float b0 = ba[col], b1 = ba[col + 1];
                v0 = 1.0f / (1.0f + expf(-(v0 + b0)));
                v1 = 1.0f / (1.0f + expf(-(v1 + b1)));
                v2 = 1.0f / (1.0f + expf(-(v2 + b0)));
                v3 = 1.0f / (1.0f + expf(-(v3 + b1)));
            }
            *reinterpret_cast<float2*>(dst + (size_t)row * DI + col) = make_float2(v0, v1);
            *reinterpret_cast<float2*>(dst + (size_t)(row + 8) * DI + col) = make_float2(v2, v3);
        }
    }
}

__global__ void __launch_bounds__(256) out_hmma(const float* __restrict__ x,
                                                float* __restrict__ out) {
    extern __shared__ __half smh[];
    float c[4][4][4];
#pragma unroll
    for (int i = 0; i < 4; i++)
#pragma unroll
        for (int j = 0; j < 4; j++)
#pragma unroll
            for (int q = 0; q < 4; q++) c[i][j][q] = 0.f;
    int n0 = blockIdx.x * 128, m0 = blockIdx.y * 128;
    hmma_gemm(g_oh, g_ol, DI, g_Woh, g_Wol, DM, m0, n0, DI, c, smh, 0);

    int tid = threadIdx.x, lane = tid & 31, wid = tid >> 5;
    int wm = wid >> 2, wn = wid & 3;
#pragma unroll
    for (int mi = 0; mi < 4; mi++) {
        int row = m0 + wm * 64 + mi * 16 + (lane >> 2);
#pragma unroll
        for (int ni = 0; ni < 4; ni++) {
            int col = n0 + wn * 32 + ni * 8 + (lane & 3) * 2;
            float2 x0 = *reinterpret_cast<const float2*>(x + (size_t)row * DM + col);
            float2 x1 = *reinterpret_cast<const float2*>(x + (size_t)(row + 8) * DM + col);
            *reinterpret_cast<float2*>(out + (size_t)row * DM + col) =
                make_float2(c[mi][ni][0] + x0.x, c[mi][ni][1] + x0.y);
            *reinterpret_cast<float2*>(out + (size_t)(row + 8) * DM + col) =
                make_float2(c[mi][ni][2] + x1.x, c[mi][ni][3] + x1.y);
        }
    }
}

// ---------------------------------------------------------------------------
// Pass A: per (b,h,chunk). G cumprod, q~=G*q, k~=knorm/G, D, U=K~^T V,
// O_intra = ((Q~K~^T).mask) V.  float4-vectorized reductions.
// ---------------------------------------------------------------------------
extern __shared__ float smemA[];
__global__ void __launch_bounds__(256) rec_intra() {
    float* sA = smemA;
    float* sQ = sA + 64 * SROW;
    float* sK = sQ + 64 * SROW;
    float* sV = sK + 64 * SROW;

    int idx = blockIdx.x;
    int c = idx % NC, bh = idx / NC;
    int b = bh / H_, h = bh % H_;
    int m0 = b * T_ + c * C_;
    int col = h * DH;
    int tid = threadIdx.x;

#pragma unroll
    for (int r = 0; r < 4; r++) {
        int e = tid + r * 256;
        int t = e >> 4; int d4 = (e & 15) * 4;
        float4 va = *reinterpret_cast<const float4*>(&g_a[(size_t)(m0 + t) * DI + col + d4]);
        *reinterpret_cast<float4*>(&sA[t * SROW + d4]) = va;
    }
    __syncthreads();
    if (tid < 64) {
        float g = 1.0f;
        for (int t = 0; t < 64; t++) { g *= sA[t * SROW + tid]; sA[t * SROW + tid] = g; }
    }
    __syncthreads();
#pragma unroll
    for (int r = 0; r < 4; r++) {
        int e = tid + r * 256;
        int t = e >> 4; int d4 = (e & 15) * 4;
        float4 vq = *reinterpret_cast<const float4*>(&g_q[(size_t)(m0 + t) * DI + col + d4]);
        float4 gg = *reinterpret_cast<const float4*>(&sA[t * SROW + d4]);
        vq.x *= gg.x; vq.y *= gg.y; vq.z *= gg.z; vq.w *= gg.w;
        *reinterpret_cast<float4*>(&sQ[t * SROW + d4]) = vq;
        *reinterpret_cast<float4*>(&g_q[(size_t)(m0 + t) * DI + col + d4]) = vq;
    }
    {
        int w = tid >> 5, l = tid & 31;
#pragma unroll
        for (int rr = 0; rr < 8; rr++) {
            int t = w * 8 + rr;
            float x0 = g_k[(size_t)(m0 + t) * DI + col + l];
            float x1 = g_k[(size_t)(m0 + t) * DI + col + l + 32];
            float s = x0 * x0 + x1 * x1;
#pragma unroll
            for (int o = 16; o; o >>= 1) s += __shfl_xor_sync(0xFFFFFFFFu, s, o);
            float inv = 1.0f / fmaxf(sqrtf(s), 1e-12f);
            sK[t * SROW + l]      = x0 * inv / sA[t * SROW + l];
            sK[t * SROW + l + 32] = x1 * inv / sA[t * SROW + l + 32];
        }
    }
#pragma unroll
    for (int r = 0; r < 4; r++) {
        int e = tid + r * 256;
        int t = e >> 4; int d4 = (e & 15) * 4;
        float4 vv = *reinterpret_cast<const float4*>(&g_v[(size_t)(m0 + t) * DI + col + d4]);
        *reinterpret_cast<float4*>(&sV[t * SROW + d4]) = vv;
    }
    if (tid < 64) g_D[(size_t)idx * 64 + tid] = sA[63 * SROW + tid];
    __syncthreads();

    int ty = tid >> 4, tx = tid & 15;
    int r0 = ty * 4, c0 = tx * 4;
    // U[j][i] = sum_s K~[s][j] V[s][i]
    {
        float acc[4][4];
#pragma unroll
        for (int a = 0; a < 4; a++)
#pragma unroll
            for (int bb2 = 0; bb2 < 4; bb2++) acc[a][bb2] = 0.f;
        for (int s = 0; s < 64; s++) {
            float4 kk = *reinterpret_cast<const float4*>(&sK[s * SROW + r0]);
            float4 vv = *reinterpret_cast<const float4*>(&sV[s * SROW + c0]);
            float ka[4] = {kk.x, kk.y, kk.z, kk.w};
            float vb[4] = {vv.x, vv.y, vv.z, vv.w};
#pragma unroll
            for (int a = 0; a < 4; a++)
#pragma unroll
                for (int bb2 = 0; bb2 < 4; bb2++) acc[a][bb2] += ka[a] * vb[bb2];
        }
#pragma unroll
        for (int a = 0; a < 4; a++) {
            float4 o4 = make_float4(acc[a][0], acc[a][1], acc[a][2], acc[a][3]);
            *reinterpret_cast<float4*>(&g_U[(size_t)idx * 4096 + (r0 + a) * 64 + c0]) = o4;
        }
    }
    // P[t][s] = sum_j Q~[t][j] K~[s][j] (float4 over j)
    {
        float acc[4][4];
#pragma unroll
        for (int a = 0; a < 4; a++)
#pragma unroll
            for (int bb2 = 0; bb2 < 4; bb2++) acc[a][bb2] = 0.f;
        for (int j = 0; j < 64; j += 4) {
            float4 qa4[4], kb4[4];
#pragma unroll
            for (int a = 0; a < 4; a++)
                qa4[a] = *reinterpret_cast<const float4*>(&sQ[(r0 + a) * SROW + j]);
#pragma unroll
            for (int bb2 = 0; bb2 < 4; bb2++)
                kb4[bb2] = *reinterpret_cast<const float4*>(&sK[(c0 + bb2) * SROW + j]);
#pragma unroll
            for (int a = 0; a < 4; a++)
#pragma unroll
                for (int bb2 = 0; bb2 < 4; bb2++) {
                    acc[a][bb2] += qa4[a].x * kb4[bb2].x;
                    acc[a][bb2] += qa4[a].y * kb4[bb2].y;
                    acc[a][bb2] += qa4[a].z * kb4[bb2].z;
                    acc[a][bb2] += qa4[a].w * kb4[bb2].w;
                }
        }
#pragma unroll
        for (int a = 0; a < 4; a++) {
#pragma unroll
            for (int bb2 = 0; bb2 < 4; bb2++)
                if (c0 + bb2 > r0 + a) acc[a][bb2] = 0.f;
            float4 o4 = make_float4(acc[a][0], acc[a][1], acc[a][2], acc[a][3]);
            *reinterpret_cast<float4*>(&sA[(r0 + a) * SROW + c0]) = o4;
        }
    }
    __syncthreads();
    // O_intra[t][i] = sum_s P[t][s] V[s][i] (float4 over s for P)
    {
        float acc[4][4];
#pragma unroll
        for (int a = 0; a < 4; a++)
#pragma unroll
            for (int bb2 = 0; bb2 < 4; bb2++) acc[a][bb2] = 0.f;
        for (int s = 0; s < 64; s += 4) {
            float4 pa4[4], vb4[4];
#pragma unroll
            for (int a = 0; a < 4; a++)
                pa4[a] = *reinterpret_cast<const float4*>(&sA[(r0 + a) * SROW + s]);
#pragma unroll
            for (int si = 0; si < 4; si++)
                vb4[si] = *reinterpret_cast<const float4*>(&sV[(s + si) * SROW + c0]);
#pragma unroll
            for (int a = 0; a < 4; a++) {
                acc[a][0] += pa4[a].x * vb4[0].x; acc[a][1] += pa4[a].x * vb4[0].y;
                acc[a][2] += pa4[a].x * vb4[0].z; acc[a][3] += pa4[a].x * vb4[0].w;
                acc[a][0] += pa4[a].y * vb4[1].x; acc[a][1] += pa4[a].y * vb4[1].y;
                acc[a][2] += pa4[a].y * vb4[1].z; acc[a][3] += pa4[a].y * vb4[1].w;
                acc[a][0] += pa4[a].z * vb4[2].x; acc[a][1] += pa4[a].z * vb4[2].y;
                acc[a][2] += pa4[a].z * vb4[2].z; acc[a][3] += pa4[a].z * vb4[2].w;
                acc[a][0] += pa4[a].w * vb4[3].x; acc[a][1] += pa4[a].w * vb4[3].y;
                acc[a][2] += pa4[a].w * vb4[3].z; acc[a][3] += pa4[a].w * vb4[3].w;
            }
        }
#pragma unroll
        for (int a = 0; a < 4; a++) {
            float4 o4 = make_float4(acc[a][0], acc[a][1], acc[a][2], acc[a][3]);
            *reinterpret_cast<float4*>(&g_o[(size_t)(m0 + r0 + a) * DI + col + c0]) = o4;
        }
    }
}

// ---------------------------------------------------------------------------
// Pass B: scan over chunks. grid (32, 8), 256 thr; float2/thread, MLP-8
// register ring prefetch.
// ---------------------------------------------------------------------------
__global__ void __launch_bounds__(256) rec_state() {
    int bh = blockIdx.x;
    int seg = blockIdx.y;
    int tid = threadIdx.x;
    int idx = seg * 512 + tid * 2;
    int j = idx >> 6;
    size_t base0 = (size_t)(bh * NC) * 4096 + idx;
    size_t dbase = (size_t)(bh * NC) * 64 + j;
    float2 S = make_float2(0.f, 0.f);
    float2 ub[8];
    float db[8];
#pragma unroll
    for (int i = 0; i < 8; i++) {
        ub[i] = *reinterpret_cast<const float2*>(&g_U[base0 + (size_t)i * 4096]);
        db[i] = g_D[dbase + (size_t)i * 64];
    }
    for (int c = 0; c < NC; c += 8) {
#pragma unroll
        for (int q = 0; q < 8; q++) {
            int cc = c + q;
            *reinterpret_cast<float2*>(&g_S[base0 + (size_t)cc * 4096]) = S;
            float2 uc = ub[q];
            float dc = db[q];
            if (cc + 8 < NC) {
                ub[q] = *reinterpret_cast<const float2*>(&g_U[base0 + (size_t)(cc + 8) * 4096]);
                db[q] = g_D[dbase + (size_t)(cc + 8) * 64];
            }
            S.x = dc * (S.x + uc.x);
            S.y = dc * (S.y + uc.y);
        }
    }
}

// ---------------------------------------------------------------------------
// Pass C: O = g_o (intra) + q~ @ S_in, written as fp16 hi/lo.
// ---------------------------------------------------------------------------
__global__ void __launch_bounds__(256) rec_inter() {
    __shared__ float sQ[64 * SROW];
    __shared__ float sS[64 * SROW];
    int idx = blockIdx.x;
    int c = idx % NC, bh = idx / NC;
    int b = bh / H_, h = bh % H_;
    int m0 = b * T_ + c * C_;
    int col = h * DH;
    int tid = threadIdx.x;
#pragma unroll
    for (int r = 0; r < 4; r++) {
        int e = tid + r * 256;
        int t = e >> 4; int d4 = (e & 15) * 4;
        *reinterpret_cast<float4*>(&sQ[t * SROW + d4]) =
            *reinterpret_cast<const float4*>(&g_q[(size_t)(m0 + t) * DI + col + d4]);
        *reinterpret_cast<float4*>(&sS[t * SROW + d4]) =
            *reinterpret_cast<const float4*>(&g_S[(size_t)idx * 4096 + t * 64 + d4]);
    }
    __syncthreads();
    int ty = tid >> 4, tx = tid & 15;
    int r0 = ty * 4, c0 = tx * 4;
    float acc[4][4];
#pragma unroll
    for (int a = 0; a < 4; a++)
#pragma unroll
        for (int bb2 = 0; bb2 < 4; bb2++) acc[a][bb2] = 0.f;
    for (int j = 0; j < 64; j += 4) {
        float4 qa4[4], sv4[4];
#pragma unroll
        for (int a = 0; a < 4; a++)
            qa4[a] = *reinterpret_cast<const float4*>(&sQ[(r0 + a) * SROW + j]);
#pragma unroll
        for (int ji = 0; ji < 4; ji++)
            sv4[ji] = *reinterpret_cast<const float4*>(&sS[(j + ji) * SROW + c0]);
#pragma unroll
        for (int a = 0; a < 4; a++) {
            acc[a][0] += qa4[a].x * sv4[0].x; acc[a][1] += qa4[a].x * sv4[0].y;
            acc[a][2] += qa4[a].x * sv4[0].z; acc[a][3] += qa4[a].x * sv4[0].w;
            acc[a][0] += qa4[a].y * sv4[1].x; acc[a][1] += qa4[a].y * sv4[1].y;
            acc[a][2] += qa4[a].y * sv4[1].z; acc[a][3] += qa4[a].y * sv4[1].w;
            acc[a][0] += qa4[a].z * sv4[2].x; acc[a][1] += qa4[a].z * sv4[2].y;
            acc[a][2] += qa4[a].z * sv4[2].z; acc[a][3] += qa4[a].z * sv4[2].w;
            acc[a][0] += qa4[a].w * sv4[3].x; acc[a][1] += qa4[a].w * sv4[3].y;
            acc[a][2] += qa4[a].w * sv4[3].z; acc[a][3] += qa4[a].w * sv4[3].w;
        }
    }
#pragma unroll
    for (int a = 0; a < 4; a++) {
        size_t off = (size_t)(m0 + r0 + a) * DI + col + c0;
        float4 cur = *reinterpret_cast<const float4*>(&g_o[off]);
        split4_store(cur.x + acc[a][0], cur.y + acc[a][1],
                     cur.z + acc[a][2], cur.w + acc[a][3], g_oh, g_ol, off);
    }
}

// ---------------------------------------------------------------------------
extern "C" void kernel_launch(void* const* d_in, const int* in_sizes, int n_in,
                              void* d_out, int out_size) {
    const float* x     = (const float*)d_in[0];
    const float* Wq    = (const float*)d_in[1];
    const float* Wk    = (const float*)d_in[2];
    const float* Wv    = (const float*)d_in[3];
    const float* Wa    = (const float*)d_in[4];
    const float* ba    = (const float*)d_in[5];
    const float* Wo    = (const float*)d_in[6];
    const float* gamma = (const float*)d_in[7];
    const float* beta  = (const float*)d_in[8];
    float* out = (float*)d_out;

    const int smemA = 4 * 64 * SROW * sizeof(float);
    cudaFuncSetAttribute(rec_intra, cudaFuncAttributeMaxDynamicSharedMemorySize, smemA);
    cudaFuncSetAttribute(proj_hmma, cudaFuncAttributeMaxDynamicSharedMemorySize, GEMM_SMEM);
    cudaFuncSetAttribute(out_hmma, cudaFuncAttributeMaxDynamicSharedMemorySize, GEMM_SMEM);

    prep_kernel<<<M_ + 5 * 512, 256>>>(x, gamma, beta, Wq, Wk, Wv, Wa, Wo);
    proj_hmma<<<dim3(16, 128), 256, GEMM_SMEM>>>(ba);
    rec_intra<<<NCHUNK, 256, smemA>>>();
    rec_state<<<dim3(32, 8), 256>>>();
    rec_inter<<<NCHUNK, 256>>>();
    out_hmma<<<dim3(8, 128), 256, GEMM_SMEM>>>(x, out);
}

// round 16
// speedup vs baseline: 1.0569x; 1.0435x over previous
#include <cuda_runtime.h>
#include <cuda_fp16.h>
#include <cstdint>
#include <math.h>

// ---------------------------------------------------------------------------
// GLA layer, GB300 (base sm_103 ISA: mma.sync HMMA path)
// prep (LN + weight splits) -> {q,k,v,a} proj (fp16-split HMMA; 1-pass v,
// 2-pass q/k, 3-pass gates; frozen 128x128/256t config) -> chunked gated
// recurrence (float4 smem, MLP-8 scan) -> out proj (1-pass) + residual
// ---------------------------------------------------------------------------
#define B_    4
#define T_    4096
#define DM    1024
#define DI    512
#define H_    8
#define DH    64
#define C_    64
#define NC    (T_ / C_)
#define M_    (B_ * T_)        // 16384
#define BH    (B_ * H_)        // 32
#define NCHUNK (BH * NC)       // 2048
#define SROW  68

// fp32 scratch
__device__ float g_q[M_ * DI];
__device__ float g_k[M_ * DI];
__device__ float g_v[M_ * DI];
__device__ float g_a[M_ * DI];
__device__ float g_o[M_ * DI];
__device__ float g_U[NCHUNK * DH * DH];
__device__ float g_S[NCHUNK * DH * DH];
__device__ float g_D[NCHUNK * DH];
// fp16 hi/lo split operands
__device__ __half g_xnh[M_ * DM], g_xnl[M_ * DM];
__device__ __half g_Wh[1024 * 2048], g_Wl[1024 * 2048];  // [K][Wq|Wk|Wv|Wa]
__device__ __half g_Woh[512 * 1024];                      // [K][N] (hi only)
__device__ __half g_oh[M_ * DI];                          // head outputs (hi only)

// ---------------------------------------------------------------------------
// PTX helpers
// ---------------------------------------------------------------------------
__device__ __forceinline__ uint32_t smem_u32(const void* p) {
    uint32_t a;
    asm("{ .reg .u64 t; cvta.to.shared.u64 t, %1; cvt.u32.u64 %0, t; }" : "=r"(a) : "l"(p));
    return a;
}
#define CP16(dst, src) asm volatile("cp.async.cg.shared.global [%0], [%1], 16;" :: "r"(dst), "l"(src))
#define CPCOMMIT()     asm volatile("cp.async.commit_group;" ::: "memory")
#define CPWAIT0()      asm volatile("cp.async.wait_group 0;" ::: "memory")

#define LDSM4(r, a) asm volatile( \
    "ldmatrix.sync.aligned.m8n8.x4.shared.b16 {%0,%1,%2,%3}, [%4];" \
    : "=r"((r)[0]), "=r"((r)[1]), "=r"((r)[2]), "=r"((r)[3]) : "r"(a))
#define LDSM4T(r, a) asm volatile( \
    "ldmatrix.sync.aligned.m8n8.x4.trans.shared.b16 {%0,%1,%2,%3}, [%4];" \
    : "=r"((r)[0]), "=r"((r)[1]), "=r"((r)[2]), "=r"((r)[3]) : "r"(a))
#define MMA16816(c, a, b0, b1) asm volatile( \
    "mma.sync.aligned.m16n8k16.row.col.f32.f16.f16.f32 " \
    "{%0,%1,%2,%3},{%4,%5,%6,%7},{%8,%9},{%0,%1,%2,%3};" \
    : "+f"((c)[0]), "+f"((c)[1]), "+f"((c)[2]), "+f"((c)[3]) \
    : "r"((a)[0]), "r"((a)[1]), "r"((a)[2]), "r"((a)[3]), "r"(b0), "r"(b1))

// vectorized hi/lo split of 4 floats -> two half2 stores each
__device__ __forceinline__ void split4_store(float f0, float f1, float f2, float f3,
                                             __half* Dh, __half* Dl, size_t o) {
    __half h0 = __float2half_rn(f0), h1 = __float2half_rn(f1);
    __half h2 = __float2half_rn(f2), h3 = __float2half_rn(f3);
    __half2 hp0; hp0.x = h0; hp0.y = h1;
    __half2 hp1; hp1.x = h2; hp1.y = h3;
    *reinterpret_cast<__half2*>(Dh + o)     = hp0;
    *reinterpret_cast<__half2*>(Dh + o + 2) = hp1;
    __half2 lp0, lp1;
    lp0.x = __float2half_rn(f0 - __half2float(h0));
    lp0.y = __float2half_rn(f1 - __half2float(h1));
    lp1.x = __float2half_rn(f2 - __half2float(h2));
    lp1.y = __float2half_rn(f3 - __half2float(h3));
    *reinterpret_cast<__half2*>(Dl + o)     = lp0;
    *reinterpret_cast<__half2*>(Dl + o + 2) = lp1;
}

// hi-only store of 4 floats -> two half2 stores
__device__ __forceinline__ void hi4_store(float f0, float f1, float f2, float f3,
                                          __half* Dh, size_t o) {
    __half2 hp0; hp0.x = __float2half_rn(f0); hp0.y = __float2half_rn(f1);
    __half2 hp1; hp1.x = __float2half_rn(f2); hp1.y = __float2half_rn(f3);
    *reinterpret_cast<__half2*>(Dh + o)     = hp0;
    *reinterpret_cast<__half2*>(Dh + o + 2) = hp1;
}

// ---------------------------------------------------------------------------
// Prep: LN -> fp16 hi/lo (blocks 0..16383) + weight splits (blocks 16384+)
// Wo gets hi-only (out GEMM is single-pass).
// ---------------------------------------------------------------------------
__global__ void __launch_bounds__(256) prep_kernel(
    const float* __restrict__ x, const float* __restrict__ gamma,
    const float* __restrict__ beta,
    const float* __restrict__ Wq, const float* __restrict__ Wk,
    const float* __restrict__ Wv, const float* __restrict__ Wa,
    const float* __restrict__ Wo)
{
    int bid = blockIdx.x;
    int tid = threadIdx.x;
    if (bid < M_) {
        int row = bid;
        const float4* xr = reinterpret_cast<const float4*>(x + (size_t)row * DM);
        float4 v = xr[tid];
        float s  = v.x + v.y + v.z + v.w;
        float sq = v.x * v.x + v.y * v.y + v.z * v.z + v.w * v.w;
#pragma unroll
        for (int o = 16; o; o >>= 1) {
            s  += __shfl_xor_sync(0xFFFFFFFFu, s, o);
            sq += __shfl_xor_sync(0xFFFFFFFFu, sq, o);
        }
        __shared__ float ss[8], ssq[8];
        int w = tid >> 5, l = tid & 31;
        if (l == 0) { ss[w] = s; ssq[w] = sq; }
        __syncthreads();
        if (tid == 0) {
            float a = 0.f, b = 0.f;
#pragma unroll
            for (int i = 0; i < 8; i++) { a += ss[i]; b += ssq[i]; }
            ss[0] = a; ssq[0] = b;
        }
        __syncthreads();
        float mu   = ss[0] * (1.0f / DM);
        float var  = ssq[0] * (1.0f / DM) - mu * mu;
        float rstd = rsqrtf(var + 1e-5f);
        float4 gg = reinterpret_cast<const float4*>(gamma)[tid];
        float4 bb = reinterpret_cast<const float4*>(beta)[tid];
        float o0 = (v.x - mu) * rstd * gg.x + bb.x;
        float o1 = (v.y - mu) * rstd * gg.y + bb.y;
        float o2 = (v.z - mu) * rstd * gg.z + bb.z;
        float o3 = (v.w - mu) * rstd * gg.w + bb.w;
        size_t base = (size_t)row * DM + tid * 4;
        split4_store(o0, o1, o2, o3, g_xnh, g_xnl, base);
    } else {
        int idx2 = bid - M_;
        int which = idx2 >> 9;          // 0..4
        int blk = idx2 & 511;
        const float* W = (which == 0) ? Wq : (which == 1) ? Wk :
                         (which == 2) ? Wv : (which == 3) ? Wa : Wo;
        int e = (blk * 256 + tid) * 4;
        if (which == 4) {
            int k = e / 1024, n = e % 1024;
            float4 v = *reinterpret_cast<const float4*>(W + e);
            hi4_store(v.x, v.y, v.z, v.w, g_Woh, (size_t)k * 1024 + n);
        } else {
            int k = e / 512, n = e % 512;
            float4 v = *reinterpret_cast<const float4*>(W + e);
            size_t dbase = (size_t)k * 2048 + which * 512 + n;
            split4_store(v.x, v.y, v.z, v.w, g_Wh, g_Wl, dbase);
        }
    }
}

// ---------------------------------------------------------------------------
// HMMA GEMM: 128x128 CTA, 8 warps (2x4), warp 64x32, k-stage 32, f32 acc,
// cp.async dbl buffer, one sync/stage. npass: 1 = AhBh; 2 = +AhBl; 3 = +AlBh.
// ---------------------------------------------------------------------------
#define ASTR 40
#define BSTR 136
#define STG_A (128 * ASTR)             // 5120 halves
#define STG_B (32 * BSTR)              // 4352 halves
#define STG_TOT (2 * STG_A + 2 * STG_B)// 18944 halves = 37888 B
#define GEMM_SMEM (2 * STG_TOT * 2)    // 75776 B (2 CTAs/SM)

__device__ __forceinline__ void hmma_prefetch(
    uint32_t base, const __half* Ah, const __half* Al, int lda,
    const __half* Bh, const __half* Bl, int ldb,
    int m0, int n0, int k0, int tid, int npass)
{
#pragma unroll
    for (int i = 0; i < 2; i++) {
        int e = tid + i * 256;
        int row = e >> 2, col = (e & 3) * 8;
        size_t ga = (size_t)(m0 + row) * lda + k0 + col;
        CP16(base + (row * ASTR + col) * 2, Ah + ga);
        if (npass == 3) CP16(base + (STG_A + row * ASTR + col) * 2, Al + ga);
        int rb = e >> 4, cb = (e & 15) * 8;
        size_t gb = (size_t)(k0 + rb) * ldb + n0 + cb;
        CP16(base + (2 * STG_A + rb * BSTR + cb) * 2, Bh + gb);
        if (npass >= 2)
            CP16(base + (2 * STG_A + STG_B + rb * BSTR + cb) * 2, Bl + gb);
    }
    CPCOMMIT();
}

__device__ __forceinline__ void hmma_gemm(
    const __half* Ah, const __half* Al, int lda,
    const __half* Bh, const __half* Bl, int ldb,
    int m0, int n0, int K, float c[4][4][4], __half* sm, int npass)
{
    int tid = threadIdx.x, lane = tid & 31, wid = tid >> 5;
    int wm = wid >> 2, wn = wid & 3;
    uint32_t smb = smem_u32(sm);
    int stages = K / 32;

    hmma_prefetch(smb, Ah, Al, lda, Bh, Bl, ldb, m0, n0, 0, tid, npass);

    for (int s = 0; s < stages; s++) {
        int buf = s & 1;
        CPWAIT0();
        __syncthreads();   // all threads done with buf^1 reads AND prefetch landed
        if (s + 1 < stages)
            hmma_prefetch(smb + (buf ^ 1) * STG_TOT * 2, Ah, Al, lda, Bh, Bl, ldb,
                          m0, n0, (s + 1) * 32, tid, npass);
        uint32_t aH = smb + buf * STG_TOT * 2;
        uint32_t bH = aH + 2 * STG_A * 2;
#pragma unroll
        for (int ks = 0; ks < 2; ks++) {
            uint32_t ah[4][4], al[4][4];
#pragma unroll
            for (int mi = 0; mi < 4; mi++) {
                uint32_t addr = aH + ((wm * 64 + mi * 16 + (lane & 15)) * ASTR
                                      + ks * 16 + (lane >> 4) * 8) * 2;
                LDSM4(ah[mi], addr);
            }
            if (npass == 3) {
#pragma unroll
                for (int mi = 0; mi < 4; mi++) {
                    uint32_t addr = aH + ((wm * 64 + mi * 16 + (lane & 15)) * ASTR
                                          + ks * 16 + (lane >> 4) * 8) * 2;
                    LDSM4(al[mi], addr + STG_A * 2);
                }
            }
            uint32_t bh[2][4], bl[2][4];
#pragma unroll
            for (int np = 0; np < 2; np++) {
                uint32_t addr = bH + ((ks * 16 + (lane & 15)) * BSTR
                                      + wn * 32 + np * 16 + (lane >> 4) * 8) * 2;
                LDSM4T(bh[np], addr);
                if (npass >= 2) LDSM4T(bl[np], addr + STG_B * 2);
            }
            if (npass == 3) {
#pragma unroll
                for (int mi = 0; mi < 4; mi++)
#pragma unroll
                    for (int ni = 0; ni < 4; ni++) {
                        int np = ni >> 1, pr = (ni & 1) * 2;
                        MMA16816(c[mi][ni], ah[mi], bh[np][pr], bh[np][pr + 1]);
                        MMA16816(c[mi][ni], ah[mi], bl[np][pr], bl[np][pr + 1]);
                        MMA16816(c[mi][ni], al[mi], bh[np][pr], bh[np][pr + 1]);
                    }
            } else if (npass == 2) {
#pragma unroll
                for (int mi = 0; mi < 4; mi++)
#pragma unroll
                    for (int ni = 0; ni < 4; ni++) {
                        int np = ni >> 1, pr = (ni & 1) * 2;
                        MMA16816(c[mi][ni], ah[mi], bh[np][pr], bh[np][pr + 1]);
                        MMA16816(c[mi][ni], ah[mi], bl[np][pr], bl[np][pr + 1]);
                    }
            } else {
#pragma unroll
                for (int mi = 0; mi < 4; mi++)
#pragma unroll
                    for (int ni = 0; ni < 4; ni++) {
                        int np = ni >> 1, pr = (ni & 1) * 2;
                        MMA16816(c[mi][ni], ah[mi], bh[np][pr], bh[np][pr + 1]);
                    }
            }
        }
        // no bottom sync: next stage's top sync protects buffer reuse
    }
}

__global__ void __launch_bounds__(256) proj_hmma(const float* __restrict__ ba) {
    extern __shared__ __half smh[];
    float c[4][4][4];
#pragma unroll
    for (int i = 0; i < 4; i++)
#pragma unroll
        for (int j = 0; j < 4; j++)
#pragma unroll
            for (int q = 0; q < 4; q++) c[i][j][q] = 0.f;
    int n0 = blockIdx.x * 128, m0 = blockIdx.y * 128;
    int which = n0 >> 9, cb = n0 & 511;
    int npass = (which == 3) ? 3 : ((which == 2) ? 1 : 2);
    hmma_gemm(g_xnh, g_xnl, DM, g_Wh, g_Wl, 2048, m0, n0, DM, c, smh, npass);

    int tid = threadIdx.x, lane = tid & 31, wid = tid >> 5;
    int wm = wid >> 2, wn = wid & 3;
    float* dst = (which == 0) ? g_q : (which == 1) ? g_k : (which == 2) ? g_v : g_a;
#pragma unroll
    for (int mi = 0; mi < 4; mi++) {
        int row = m0 + wm * 64 + mi * 16 + (lane >> 2);
#pragma unroll
        for (int ni = 0; ni < 4; ni++) {
            int col = cb + wn * 32 + ni * 8 + (lane & 3) * 2;
            float v0 = c[mi][ni][0], v1 = c[mi][ni][1];
            float v2 = c[mi][ni][2], v3 = c[mi][ni][3];
            if (which == 3) {
                float b0 = ba[col], b1 = ba[col + 1];
                v0 = 1.0f / (1.0f + expf(-(v0 + b0)));
                v1 = 1.0f / (1.0f + expf(-(v1 + b1)));
                v2 = 1.0f / (1.0f + expf(-(v2 + b0)));
                v3 = 1.0f / (1.0f + expf(-(v3 + b1)));
            }
            *reinterpret_cast<float2*>(dst + (size_t)row * DI + col) = make_float2(v0, v1);
            *reinterpret_cast<float2*>(dst + (size_t)(row + 8) * DI + col) = make_float2(v2, v3);
        }
    }
}

__global__ void __launch_bounds__(256) out_hmma(const float* __restrict__ x,
                                                float* __restrict__ out) {
    extern __shared__ __half smh[];
    float c[4][4][4];
#pragma unroll
    for (int i = 0; i < 4; i++)
#pragma unroll
        for (int j = 0; j < 4; j++)
#pragma unroll
            for (int q = 0; q < 4; q++) c[i][j][q] = 0.f;
    int n0 = blockIdx.x * 128, m0 = blockIdx.y * 128;
    hmma_gemm(g_oh, g_oh, DI, g_Woh, g_Woh, DM, m0, n0, DI, c, smh, 1);

    int tid = threadIdx.x, lane = tid & 31, wid = tid >> 5;
    int wm = wid >> 2, wn = wid & 3;
#pragma unroll
    for (int mi = 0; mi < 4; mi++) {
        int row = m0 + wm * 64 + mi * 16 + (lane >> 2);
#pragma unroll
        for (int ni = 0; ni < 4; ni++) {
            int col = n0 + wn * 32 + ni * 8 + (lane & 3) * 2;
            float2 x0 = *reinterpret_cast<const float2*>(x + (size_t)row * DM + col);
            float2 x1 = *reinterpret_cast<const float2*>(x + (size_t)(row + 8) * DM + col);
            *reinterpret_cast<float2*>(out + (size_t)row * DM + col) =
                make_float2(c[mi][ni][0] + x0.x, c[mi][ni][1] + x0.y);
            *reinterpret_cast<float2*>(out + (size_t)(row + 8) * DM + col) =
                make_float2(c[mi][ni][2] + x1.x, c[mi][ni][3] + x1.y);
        }
    }
}

// ---------------------------------------------------------------------------
// Pass A: per (b,h,chunk). G cumprod, q~=G*q, k~=knorm/G, D, U=K~^T V,
// O_intra = ((Q~K~^T).mask) V.  float4-vectorized reductions.
// ---------------------------------------------------------------------------
extern __shared__ float smemA[];
__global__ void __launch_bounds__(256) rec_intra() {
    float* sA = smemA;
    float* sQ = sA + 64 * SROW;
    float* sK = sQ + 64 * SROW;
    float* sV = sK + 64 * SROW;

    int idx = blockIdx.x;
    int c = idx % NC, bh = idx / NC;
    int b = bh / H_, h = bh % H_;
    int m0 = b * T_ + c * C_;
    int col = h * DH;
    int tid = threadIdx.x;

#pragma unroll
    for (int r = 0; r < 4; r++) {
        int e = tid + r * 256;
        int t = e >> 4; int d4 = (e & 15) * 4;
        float4 va = *reinterpret_cast<const float4*>(&g_a[(size_t)(m0 + t) * DI + col + d4]);
        *reinterpret_cast<float4*>(&sA[t * SROW + d4]) = va;
    }
    __syncthreads();
    if (tid < 64) {
        float g = 1.0f;
        for (int t = 0; t < 64; t++) { g *= sA[t * SROW + tid]; sA[t * SROW + tid] = g; }
    }
    __syncthreads();
#pragma unroll
    for (int r = 0; r < 4; r++) {
        int e = tid + r * 256;
        int t = e >> 4; int d4 = (e & 15) * 4;
        float4 vq = *reinterpret_cast<const float4*>(&g_q[(size_t)(m0 + t) * DI + col + d4]);
        float4 gg = *reinterpret_cast<const float4*>(&sA[t * SROW + d4]);
        vq.x *= gg.x; vq.y *= gg.y; vq.z *= gg.z; vq.w *= gg.w;
        *reinterpret_cast<float4*>(&sQ[t * SROW + d4]) = vq;
        *reinterpret_cast<float4*>(&g_q[(size_t)(m0 + t) * DI + col + d4]) = vq;
    }
    {
        int w = tid >> 5, l = tid & 31;
#pragma unroll
        for (int rr = 0; rr < 8; rr++) {
            int t = w * 8 + rr;
            float x0 = g_k[(size_t)(m0 + t) * DI + col + l];
            float x1 = g_k[(size_t)(m0 + t) * DI + col + l + 32];
            float s = x0 * x0 + x1 * x1;
#pragma unroll
            for (int o = 16; o; o >>= 1) s += __shfl_xor_sync(0xFFFFFFFFu, s, o);
            float inv = 1.0f / fmaxf(sqrtf(s), 1e-12f);
            sK[t * SROW + l]      = x0 * inv / sA[t * SROW + l];
            sK[t * SROW + l + 32] = x1 * inv / sA[t * SROW + l + 32];
        }
    }
#pragma unroll
    for (int r = 0; r < 4; r++) {
        int e = tid + r * 256;
        int t = e >> 4; int d4 = (e & 15) * 4;
        float4 vv = *reinterpret_cast<const float4*>(&g_v[(size_t)(m0 + t) * DI + col + d4]);
        *reinterpret_cast<float4*>(&sV[t * SROW + d4]) = vv;
    }
    if (tid < 64) g_D[(size_t)idx * 64 + tid] = sA[63 * SROW + tid];
    __syncthreads();

    int ty = tid >> 4, tx = tid & 15;
    int r0 = ty * 4, c0 = tx * 4;
    // U[j][i] = sum_s K~[s][j] V[s][i]
    {
        float acc[4][4];
#pragma unroll
        for (int a = 0; a < 4; a++)
#pragma unroll
            for (int bb2 = 0; bb2 < 4; bb2++) acc[a][bb2] = 0.f;
        for (int s = 0; s < 64; s++) {
            float4 kk = *reinterpret_cast<const float4*>(&sK[s * SROW + r0]);
            float4 vv = *reinterpret_cast<const float4*>(&sV[s * SROW + c0]);
            float ka[4] = {kk.x, kk.y, kk.z, kk.w};
            float vb[4] = {vv.x, vv.y, vv.z, vv.w};
#pragma unroll
            for (int a = 0; a < 4; a++)
#pragma unroll
                for (int bb2 = 0; bb2 < 4; bb2++) acc[a][bb2] += ka[a] * vb[bb2];
        }
#pragma unroll
        for (int a = 0; a < 4; a++) {
            float4 o4 = make_float4(acc[a][0], acc[a][1], acc[a][2], acc[a][3]);
            *reinterpret_cast<float4*>(&g_U[(size_t)idx * 4096 + (r0 + a) * 64 + c0]) = o4;
        }
    }
    // P[t][s] = sum_j Q~[t][j] K~[s][j] (float4 over j)
    {
        float acc[4][4];
#pragma unroll
        for (int a = 0; a < 4; a++)
#pragma unroll
            for (int bb2 = 0; bb2 < 4; bb2++) acc[a][bb2] = 0.f;
        for (int j = 0; j < 64; j += 4) {
            float4 qa4[4], kb4[4];
#pragma unroll
            for (int a = 0; a < 4; a++)
                qa4[a] = *reinterpret_cast<const float4*>(&sQ[(r0 + a) * SROW + j]);
#pragma unroll
            for (int bb2 = 0; bb2 < 4; bb2++)
                kb4[bb2] = *reinterpret_cast<const float4*>(&sK[(c0 + bb2) * SROW + j]);
#pragma unroll
            for (int a = 0; a < 4; a++)
#pragma unroll
                for (int bb2 = 0; bb2 < 4; bb2++) {
                    acc[a][bb2] += qa4[a].x * kb4[bb2].x;
                    acc[a][bb2] += qa4[a].y * kb4[bb2].y;
                    acc[a][bb2] += qa4[a].z * kb4[bb2].z;
                    acc[a][bb2] += qa4[a].w * kb4[bb2].w;
                }
        }
#pragma unroll
        for (int a = 0; a < 4; a++) {
#pragma unroll
            for (int bb2 = 0; bb2 < 4; bb2++)
                if (c0 + bb2 > r0 + a) acc[a][bb2] = 0.f;
            float4 o4 = make_float4(acc[a][0], acc[a][1], acc[a][2], acc[a][3]);
            *reinterpret_cast<float4*>(&sA[(r0 + a) * SROW + c0]) = o4;
        }
    }
    __syncthreads();
    // O_intra[t][i] = sum_s P[t][s] V[s][i] (float4 over s for P)
    {
        float acc[4][4];
#pragma unroll
        for (int a = 0; a < 4; a++)
#pragma unroll
            for (int bb2 = 0; bb2 < 4; bb2++) acc[a][bb2] = 0.f;
        for (int s = 0; s < 64; s += 4) {
            float4 pa4[4], vb4[4];
#pragma unroll
            for (int a = 0; a < 4; a++)
                pa4[a] = *reinterpret_cast<const float4*>(&sA[(r0 + a) * SROW + s]);
#pragma unroll
            for (int si = 0; si < 4; si++)
                vb4[si] = *reinterpret_cast<const float4*>(&sV[(s + si) * SROW + c0]);
#pragma unroll
            for (int a = 0; a < 4; a++) {
                acc[a][0] += pa4[a].x * vb4[0].x; acc[a][1] += pa4[a].x * vb4[0].y;
                acc[a][2] += pa4[a].x * vb4[0].z; acc[a][3] += pa4[a].x * vb4[0].w;
                acc[a][0] += pa4[a].y * vb4[1].x; acc[a][1] += pa4[a].y * vb4[1].y;
                acc[a][2] += pa4[a].y * vb4[1].z; acc[a][3] += pa4[a].y * vb4[1].w;
                acc[a][0] += pa4[a].z * vb4[2].x; acc[a][1] += pa4[a].z * vb4[2].y;
                acc[a][2] += pa4[a].z * vb4[2].z; acc[a][3] += pa4[a].z * vb4[2].w;
                acc[a][0] += pa4[a].w * vb4[3].x; acc[a][1] += pa4[a].w * vb4[3].y;
                acc[a][2] += pa4[a].w * vb4[3].z; acc[a][3] += pa4[a].w * vb4[3].w;
            }
        }
#pragma unroll
        for (int a = 0; a < 4; a++) {
            float4 o4 = make_float4(acc[a][0], acc[a][1], acc[a][2], acc[a][3]);
            *reinterpret_cast<float4*>(&g_o[(size_t)(m0 + r0 + a) * DI + col + c0]) = o4;
        }
    }
}

// ---------------------------------------------------------------------------
// Pass B: scan over chunks. grid (32, 8), 256 thr; float2/thread, MLP-8
// register ring prefetch.
// ---------------------------------------------------------------------------
__global__ void __launch_bounds__(256) rec_state() {
    int bh = blockIdx.x;
    int seg = blockIdx.y;
    int tid = threadIdx.x;
    int idx = seg * 512 + tid * 2;
    int j = idx >> 6;
    size_t base0 = (size_t)(bh * NC) * 4096 + idx;
    size_t dbase = (size_t)(bh * NC) * 64 + j;
    float2 S = make_float2(0.f, 0.f);
    float2 ub[8];
    float db[8];
#pragma unroll
    for (int i = 0; i < 8; i++) {
        ub[i] = *reinterpret_cast<const float2*>(&g_U[base0 + (size_t)i * 4096]);
        db[i] = g_D[dbase + (size_t)i * 64];
    }
    for (int c = 0; c < NC; c += 8) {
#pragma unroll
        for (int q = 0; q < 8; q++) {
            int cc = c + q;
            *reinterpret_cast<float2*>(&g_S[base0 + (size_t)cc * 4096]) = S;
            float2 uc = ub[q];
            float dc = db[q];
            if (cc + 8 < NC) {
                ub[q] = *reinterpret_cast<const float2*>(&g_U[base0 + (size_t)(cc + 8) * 4096]);
                db[q] = g_D[dbase + (size_t)(cc + 8) * 64];
            }
            S.x = dc * (S.x + uc.x);
            S.y = dc * (S.y + uc.y);
        }
    }
}

// ---------------------------------------------------------------------------
// Pass C: O = g_o (intra) + q~ @ S_in, written as fp16 hi only.
// ---------------------------------------------------------------------------
__global__ void __launch_bounds__(256) rec_inter() {
    __shared__ float sQ[64 * SROW];
    __shared__ float sS[64 * SROW];
    int idx = blockIdx.x;
    int c = idx % NC, bh = idx / NC;
    int b = bh / H_, h = bh % H_;
    int m0 = b * T_ + c * C_;
    int col = h * DH;
    int tid = threadIdx.x;
#pragma unroll
    for (int r = 0; r < 4; r++) {
        int e = tid + r * 256;
        int t = e >> 4; int d4 = (e & 15) * 4;
        *reinterpret_cast<float4*>(&sQ[t * SROW + d4]) =
            *reinterpret_cast<const float4*>(&g_q[(size_t)(m0 + t) * DI + col + d4]);
        *reinterpret_cast<float4*>(&sS[t * SROW + d4]) =
            *reinterpret_cast<const float4*>(&g_S[(size_t)idx * 4096 + t * 64 + d4]);
    }
    __syncthreads();
    int ty = tid >> 4, tx = tid & 15;
    int r0 = ty * 4, c0 = tx * 4;
    float acc[4][4];
#pragma unroll
    for (int a = 0; a < 4; a++)
#pragma unroll
        for (int bb2 = 0; bb2 < 4; bb2++) acc[a][bb2] = 0.f;
    for (int j = 0; j < 64; j += 4) {
        float4 qa4[4], sv4[4];
#pragma unroll
        for (int a = 0; a < 4; a++)
            qa4[a] = *reinterpret_cast<const float4*>(&sQ[(r0 + a) * SROW + j]);
#pragma unroll
        for (int ji = 0; ji < 4; ji++)
            sv4[ji] = *reinterpret_cast<const float4*>(&sS[(j + ji) * SROW + c0]);
#pragma unroll
        for (int a = 0; a < 4; a++) {
            acc[a][0] += qa4[a].x * sv4[0].x; acc[a][1] += qa4[a].x * sv4[0].y;
            acc[a][2] += qa4[a].x * sv4[0].z; acc[a][3] += qa4[a].x * sv4[0].w;
            acc[a][0] += qa4[a].y * sv4[1].x; acc[a][1] += qa4[a].y * sv4[1].y;
            acc[a][2] += qa4[a].y * sv4[1].z; acc[a][3] += qa4[a].y * sv4[1].w;
            acc[a][0] += qa4[a].z * sv4[2].x; acc[a][1] += qa4[a].z * sv4[2].y;
            acc[a][2] += qa4[a].z * sv4[2].z; acc[a][3] += qa4[a].z * sv4[2].w;
            acc[a][0] += qa4[a].w * sv4[3].x; acc[a][1] += qa4[a].w * sv4[3].y;
            acc[a][2] += qa4[a].w * sv4[3].z; acc[a][3] += qa4[a].w * sv4[3].w;
        }
    }
#pragma unroll
    for (int a = 0; a < 4; a++) {
        size_t off = (size_t)(m0 + r0 + a) * DI + col + c0;
        float4 cur = *reinterpret_cast<const float4*>(&g_o[off]);
        hi4_store(cur.x + acc[a][0], cur.y + acc[a][1],
                  cur.z + acc[a][2], cur.w + acc[a][3], g_oh, off);
    }
}

// ---------------------------------------------------------------------------
extern "C" void kernel_launch(void* const* d_in, const int* in_sizes, int n_in,
                              void* d_out, int out_size) {
    const float* x     = (const float*)d_in[0];
    const float* Wq    = (const float*)d_in[1];
    const float* Wk    = (const float*)d_in[2];
    const float* Wv    = (const float*)d_in[3];
    const float* Wa    = (const float*)d_in[4];
    const float* ba    = (const float*)d_in[5];
    const float* Wo    = (const float*)d_in[6];
    const float* gamma = (const float*)d_in[7];
    const float* beta  = (const float*)d_in[8];
    float* out = (float*)d_out;

    const int smemA = 4 * 64 * SROW * sizeof(float);
    cudaFuncSetAttribute(rec_intra, cudaFuncAttributeMaxDynamicSharedMemorySize, smemA);
    cudaFuncSetAttribute(proj_hmma, cudaFuncAttributeMaxDynamicSharedMemorySize, GEMM_SMEM);
    cudaFuncSetAttribute(out_hmma, cudaFuncAttributeMaxDynamicSharedMemorySize, GEMM_SMEM);

    prep_kernel<<<M_ + 5 * 512, 256>>>(x, gamma, beta, Wq, Wk, Wv, Wa, Wo);
    proj_hmma<<<dim3(16, 128), 256, GEMM_SMEM>>>(ba);
    rec_intra<<<NCHUNK, 256, smemA>>>();
    rec_state<<<dim3(32, 8), 256>>>();
    rec_inter<<<NCHUNK, 256>>>();
    out_hmma<<<dim3(8, 128), 256, GEMM_SMEM>>>(x, out);
}

// round 17
// speedup vs baseline: 1.1531x; 1.0911x over previous
#include <cuda_runtime.h>
#include <cuda_fp16.h>
#include <cstdint>
#include <math.h>

// ---------------------------------------------------------------------------
// GLA layer, GB300 (base sm_103 ISA: mma.sync HMMA path)
// prep (LN + weight splits) -> {q,k,v,a} proj (fp16-split HMMA; 1-pass q/k/v,
// 3-pass gates; frozen 128x128/256t config) -> chunked gated recurrence
// (float4 smem, MLP-8 scan) -> out proj (1-pass) + residual
// ---------------------------------------------------------------------------
#define B_    4
#define T_    4096
#define DM    1024
#define DI    512
#define H_    8
#define DH    64
#define C_    64
#define NC    (T_ / C_)
#define M_    (B_ * T_)        // 16384
#define BH    (B_ * H_)        // 32
#define NCHUNK (BH * NC)       // 2048
#define SROW  68

// fp32 scratch
__device__ float g_q[M_ * DI];
__device__ float g_k[M_ * DI];
__device__ float g_v[M_ * DI];
__device__ float g_a[M_ * DI];
__device__ float g_o[M_ * DI];
__device__ float g_U[NCHUNK * DH * DH];
__device__ float g_S[NCHUNK * DH * DH];
__device__ float g_D[NCHUNK * DH];
// fp16 hi/lo split operands
__device__ __half g_xnh[M_ * DM], g_xnl[M_ * DM];
__device__ __half g_Wh[1024 * 2048], g_Wl[1024 * 2048];  // [K][Wq|Wk|Wv|Wa]
__device__ __half g_Woh[512 * 1024];                      // [K][N] (hi only)
__device__ __half g_oh[M_ * DI];                          // head outputs (hi only)

// ---------------------------------------------------------------------------
// PTX helpers
// ---------------------------------------------------------------------------
__device__ __forceinline__ uint32_t smem_u32(const void* p) {
    uint32_t a;
    asm("{ .reg .u64 t; cvta.to.shared.u64 t, %1; cvt.u32.u64 %0, t; }" : "=r"(a) : "l"(p));
    return a;
}
#define CP16(dst, src) asm volatile("cp.async.cg.shared.global [%0], [%1], 16;" :: "r"(dst), "l"(src))
#define CPCOMMIT()     asm volatile("cp.async.commit_group;" ::: "memory")
#define CPWAIT0()      asm volatile("cp.async.wait_group 0;" ::: "memory")

#define LDSM4(r, a) asm volatile( \
    "ldmatrix.sync.aligned.m8n8.x4.shared.b16 {%0,%1,%2,%3}, [%4];" \
    : "=r"((r)[0]), "=r"((r)[1]), "=r"((r)[2]), "=r"((r)[3]) : "r"(a))
#define LDSM4T(r, a) asm volatile( \
    "ldmatrix.sync.aligned.m8n8.x4.trans.shared.b16 {%0,%1,%2,%3}, [%4];" \
    : "=r"((r)[0]), "=r"((r)[1]), "=r"((r)[2]), "=r"((r)[3]) : "r"(a))
#define MMA16816(c, a, b0, b1) asm volatile( \
    "mma.sync.aligned.m16n8k16.row.col.f32.f16.f16.f32 " \
    "{%0,%1,%2,%3},{%4,%5,%6,%7},{%8,%9},{%0,%1,%2,%3};" \
    : "+f"((c)[0]), "+f"((c)[1]), "+f"((c)[2]), "+f"((c)[3]) \
    : "r"((a)[0]), "r"((a)[1]), "r"((a)[2]), "r"((a)[3]), "r"(b0), "r"(b1))

// vectorized hi/lo split of 4 floats -> two half2 stores each
__device__ __forceinline__ void split4_store(float f0, float f1, float f2, float f3,
                                             __half* Dh, __half* Dl, size_t o) {
    __half h0 = __float2half_rn(f0), h1 = __float2half_rn(f1);
    __half h2 = __float2half_rn(f2), h3 = __float2half_rn(f3);
    __half2 hp0; hp0.x = h0; hp0.y = h1;
    __half2 hp1; hp1.x = h2; hp1.y = h3;
    *reinterpret_cast<__half2*>(Dh + o)     = hp0;
    *reinterpret_cast<__half2*>(Dh + o + 2) = hp1;
    __half2 lp0, lp1;
    lp0.x = __float2half_rn(f0 - __half2float(h0));
    lp0.y = __float2half_rn(f1 - __half2float(h1));
    lp1.x = __float2half_rn(f2 - __half2float(h2));
    lp1.y = __float2half_rn(f3 - __half2float(h3));
    *reinterpret_cast<__half2*>(Dl + o)     = lp0;
    *reinterpret_cast<__half2*>(Dl + o + 2) = lp1;
}

// hi-only store of 4 floats -> two half2 stores
__device__ __forceinline__ void hi4_store(float f0, float f1, float f2, float f3,
                                          __half* Dh, size_t o) {
    __half2 hp0; hp0.x = __float2half_rn(f0); hp0.y = __float2half_rn(f1);
    __half2 hp1; hp1.x = __float2half_rn(f2); hp1.y = __float2half_rn(f3);
    *reinterpret_cast<__half2*>(Dh + o)     = hp0;
    *reinterpret_cast<__half2*>(Dh + o + 2) = hp1;
}

// ---------------------------------------------------------------------------
// Prep: LN -> fp16 hi/lo (blocks 0..16383) + weight splits (blocks 16384+)
// Wo gets hi-only (out GEMM is single-pass).
// ---------------------------------------------------------------------------
__global__ void __launch_bounds__(256) prep_kernel(
    const float* __restrict__ x, const float* __restrict__ gamma,
    const float* __restrict__ beta,
    const float* __restrict__ Wq, const float* __restrict__ Wk,
    const float* __restrict__ Wv, const float* __restrict__ Wa,
    const float* __restrict__ Wo)
{
    int bid = blockIdx.x;
    int tid = threadIdx.x;
    if (bid < M_) {
        int row = bid;
        const float4* xr = reinterpret_cast<const float4*>(x + (size_t)row * DM);
        float4 v = xr[tid];
        float s  = v.x + v.y + v.z + v.w;
        float sq = v.x * v.x + v.y * v.y + v.z * v.z + v.w * v.w;
#pragma unroll
        for (int o = 16; o; o >>= 1) {
            s  += __shfl_xor_sync(0xFFFFFFFFu, s, o);
            sq += __shfl_xor_sync(0xFFFFFFFFu, sq, o);
        }
        __shared__ float ss[8], ssq[8];
        int w = tid >> 5, l = tid & 31;
        if (l == 0) { ss[w] = s; ssq[w] = sq; }
        __syncthreads();
        if (tid == 0) {
            float a = 0.f, b = 0.f;
#pragma unroll
            for (int i = 0; i < 8; i++) { a += ss[i]; b += ssq[i]; }
            ss[0] = a; ssq[0] = b;
        }
        __syncthreads();
        float mu   = ss[0] * (1.0f / DM);
        float var  = ssq[0] * (1.0f / DM) - mu * mu;
        float rstd = rsqrtf(var + 1e-5f);
        float4 gg = reinterpret_cast<const float4*>(gamma)[tid];
        float4 bb = reinterpret_cast<const float4*>(beta)[tid];
        float o0 = (v.x - mu) * rstd * gg.x + bb.x;
        float o1 = (v.y - mu) * rstd * gg.y + bb.y;
        float o2 = (v.z - mu) * rstd * gg.z + bb.z;
        float o3 = (v.w - mu) * rstd * gg.w + bb.w;
        size_t base = (size_t)row * DM + tid * 4;
        split4_store(o0, o1, o2, o3, g_xnh, g_xnl, base);
    } else {
        int idx2 = bid - M_;
        int which = idx2 >> 9;          // 0..4
        int blk = idx2 & 511;
        const float* W = (which == 0) ? Wq : (which == 1) ? Wk :
                         (which == 2) ? Wv : (which == 3) ? Wa : Wo;
        int e = (blk * 256 + tid) * 4;
        if (which == 4) {
            int k = e / 1024, n = e % 1024;
            float4 v = *reinterpret_cast<const float4*>(W + e);
            hi4_store(v.x, v.y, v.z, v.w, g_Woh, (size_t)k * 1024 + n);
        } else {
            int k = e / 512, n = e % 512;
            float4 v = *reinterpret_cast<const float4*>(W + e);
            size_t dbase = (size_t)k * 2048 + which * 512 + n;
            split4_store(v.x, v.y, v.z, v.w, g_Wh, g_Wl, dbase);
        }
    }
}

// ---------------------------------------------------------------------------
// HMMA GEMM: 128x128 CTA, 8 warps (2x4), warp 64x32, k-stage 32, f32 acc,
// cp.async dbl buffer, one sync/stage. npass: 1 = AhBh; 2 = +AhBl; 3 = +AlBh.
// ---------------------------------------------------------------------------
#define ASTR 40
#define BSTR 136
#define STG_A (128 * ASTR)             // 5120 halves
#define STG_B (32 * BSTR)              // 4352 halves
#define STG_TOT (2 * STG_A + 2 * STG_B)// 18944 halves = 37888 B
#define GEMM_SMEM (2 * STG_TOT * 2)    // 75776 B (2 CTAs/SM)

__device__ __forceinline__ void hmma_prefetch(
    uint32_t base, const __half* Ah, const __half* Al, int lda,
    const __half* Bh, const __half* Bl, int ldb,
    int m0, int n0, int k0, int tid, int npass)
{
#pragma unroll
    for (int i = 0; i < 2; i++) {
        int e = tid + i * 256;
        int row = e >> 2, col = (e & 3) * 8;
        size_t ga = (size_t)(m0 + row) * lda + k0 + col;
        CP16(base + (row * ASTR + col) * 2, Ah + ga);
        if (npass == 3) CP16(base + (STG_A + row * ASTR + col) * 2, Al + ga);
        int rb = e >> 4, cb = (e & 15) * 8;
        size_t gb = (size_t)(k0 + rb) * ldb + n0 + cb;
        CP16(base + (2 * STG_A + rb * BSTR + cb) * 2, Bh + gb);
        if (npass >= 2)
            CP16(base + (2 * STG_A + STG_B + rb * BSTR + cb) * 2, Bl + gb);
    }
    CPCOMMIT();
}

__device__ __forceinline__ void hmma_gemm(
    const __half* Ah, const __half* Al, int lda,
    const __half* Bh, const __half* Bl, int ldb,
    int m0, int n0, int K, float c[4][4][4], __half* sm, int npass)
{
    int tid = threadIdx.x, lane = tid & 31, wid = tid >> 5;
    int wm = wid >> 2, wn = wid & 3;
    uint32_t smb = smem_u32(sm);
    int stages = K / 32;

    hmma_prefetch(smb, Ah, Al, lda, Bh, Bl, ldb, m0, n0, 0, tid, npass);

    for (int s = 0; s < stages; s++) {
        int buf = s & 1;
        CPWAIT0();
        __syncthreads();   // all threads done with buf^1 reads AND prefetch landed
        if (s + 1 < stages)
            hmma_prefetch(smb + (buf ^ 1) * STG_TOT * 2, Ah, Al, lda, Bh, Bl, ldb,
                          m0, n0, (s + 1) * 32, tid, npass);
        uint32_t aH = smb + buf * STG_TOT * 2;
        uint32_t bH = aH + 2 * STG_A * 2;
#pragma unroll
        for (int ks = 0; ks < 2; ks++) {
            uint32_t ah[4][4], al[4][4];
#pragma unroll
            for (int mi = 0; mi < 4; mi++) {
                uint32_t addr = aH + ((wm * 64 + mi * 16 + (lane & 15)) * ASTR
                                      + ks * 16 + (lane >> 4) * 8) * 2;
                LDSM4(ah[mi], addr);
            }
            if (npass == 3) {
#pragma unroll
                for (int mi = 0; mi < 4; mi++) {
                    uint32_t addr = aH + ((wm * 64 + mi * 16 + (lane & 15)) * ASTR
                                          + ks * 16 + (lane >> 4) * 8) * 2;
                    LDSM4(al[mi], addr + STG_A * 2);
                }
            }
            uint32_t bh[2][4], bl[2][4];
#pragma unroll
            for (int np = 0; np < 2; np++) {
                uint32_t addr = bH + ((ks * 16 + (lane & 15)) * BSTR
                                      + wn * 32 + np * 16 + (lane >> 4) * 8) * 2;
                LDSM4T(bh[np], addr);
                if (npass >= 2) LDSM4T(bl[np], addr + STG_B * 2);
            }
            if (npass == 3) {
#pragma unroll
                for (int mi = 0; mi < 4; mi++)
#pragma unroll
                    for (int ni = 0; ni < 4; ni++) {
                        int np = ni >> 1, pr = (ni & 1) * 2;
                        MMA16816(c[mi][ni], ah[mi], bh[np][pr], bh[np][pr + 1]);
                        MMA16816(c[mi][ni], ah[mi], bl[np][pr], bl[np][pr + 1]);
                        MMA16816(c[mi][ni], al[mi], bh[np][pr], bh[np][pr + 1]);
                    }
            } else if (npass == 2) {
#pragma unroll
                for (int mi = 0; mi < 4; mi++)
#pragma unroll
                    for (int ni = 0; ni < 4; ni++) {
                        int np = ni >> 1, pr = (ni & 1) * 2;
                        MMA16816(c[mi][ni], ah[mi], bh[np][pr], bh[np][pr + 1]);
                        MMA16816(c[mi][ni], ah[mi], bl[np][pr], bl[np][pr + 1]);
                    }
            } else {
#pragma unroll
                for (int mi = 0; mi < 4; mi++)
#pragma unroll
                    for (int ni = 0; ni < 4; ni++) {
                        int np = ni >> 1, pr = (ni & 1) * 2;
                        MMA16816(c[mi][ni], ah[mi], bh[np][pr], bh[np][pr + 1]);
                    }
            }
        }
        // no bottom sync: next stage's top sync protects buffer reuse
    }
}

__global__ void __launch_bounds__(256) proj_hmma(const float* __restrict__ ba) {
    extern __shared__ __half smh[];
    float c[4][4][4];
#pragma unroll
    for (int i = 0; i < 4; i++)
#pragma unroll
        for (int j = 0; j < 4; j++)
#pragma unroll
            for (int q = 0; q < 4; q++) c[i][j][q] = 0.f;
    int n0 = blockIdx.x * 128, m0 = blockIdx.y * 128;
    int which = n0 >> 9, cb = n0 & 511;
    int npass = (which == 3) ? 3 : 1;   // gates full 3-pass; q/k/v single-pass
    hmma_gemm(g_xnh, g_xnl, DM, g_Wh, g_Wl, 2048, m0, n0, DM, c, smh, npass);

    int tid = threadIdx.x, lane = tid & 31, wid = tid >> 5;
    int wm = wid >> 2, wn = wid & 3;
    float* dst = (which == 0) ? g_q : (which == 1) ? g_k : (which == 2) ? g_v : g_a;
#pragma unroll
    for (int mi = 0; mi < 4; mi++) {
        int row = m0 + wm * 64 + mi * 16 + (lane >> 2);
#pragma unroll
        for (int ni = 0; ni < 4; ni++) {
            int col = cb + wn * 32 + ni * 8 + (lane & 3) * 2;
            float v0 = c[mi][ni][0], v1 = c[mi][ni][1];
            float v2 = c[mi][ni][2], v3 = c[mi][ni][3];
            if (which == 3) {
                float b0 = ba[col], b1 = ba[col + 1];
                v0 = 1.0f / (1.0f + expf(-(v0 + b0)));
                v1 = 1.0f / (1.0f + expf(-(v1 + b1)));
                v2 = 1.0f / (1.0f + expf(-(v2 + b0)));
                v3 = 1.0f / (1.0f + expf(-(v3 + b1)));
            }
            *reinterpret_cast<float2*>(dst + (size_t)row * DI + col) = make_float2(v0, v1);
            *reinterpret_cast<float2*>(dst + (size_t)(row + 8) * DI + col) = make_float2(v2, v3);
        }
    }
}

__global__ void __launch_bounds__(256) out_hmma(const float* __restrict__ x,
                                                float* __restrict__ out) {
    extern __shared__ __half smh[];
    float c[4][4][4];
#pragma unroll
    for (int i = 0; i < 4; i++)
#pragma unroll
        for (int j = 0; j < 4; j++)
#pragma unroll
            for (int q = 0; q < 4; q++) c[i][j][q] = 0.f;
    int n0 = blockIdx.x * 128, m0 = blockIdx.y * 128;
    hmma_gemm(g_oh, g_oh, DI, g_Woh, g_Woh, DM, m0, n0, DI, c, smh, 1);

    int tid = threadIdx.x, lane = tid & 31, wid = tid >> 5;
    int wm = wid >> 2, wn = wid & 3;
#pragma unroll
    for (int mi = 0; mi < 4; mi++) {
        int row = m0 + wm * 64 + mi * 16 + (lane >> 2);
#pragma unroll
        for (int ni = 0; ni < 4; ni++) {
            int col = n0 + wn * 32 + ni * 8 + (lane & 3) * 2;
            float2 x0 = *reinterpret_cast<const float2*>(x + (size_t)row * DM + col);
            float2 x1 = *reinterpret_cast<const float2*>(x + (size_t)(row + 8) * DM + col);
            *reinterpret_cast<float2*>(out + (size_t)row * DM + col) =
                make_float2(c[mi][ni][0] + x0.x, c[mi][ni][1] + x0.y);
            *reinterpret_cast<float2*>(out + (size_t)(row + 8) * DM + col) =
                make_float2(c[mi][ni][2] + x1.x, c[mi][ni][3] + x1.y);
        }
    }
}

// ---------------------------------------------------------------------------
// Pass A: per (b,h,chunk). G cumprod, q~=G*q, k~=knorm/G, D, U=K~^T V,
// O_intra = ((Q~K~^T).mask) V.  float4-vectorized reductions.
// ---------------------------------------------------------------------------
extern __shared__ float smemA[];
__global__ void __launch_bounds__(256) rec_intra() {
    float* sA = smemA;
    float* sQ = sA + 64 * SROW;
    float* sK = sQ + 64 * SROW;
    float* sV = sK + 64 * SROW;

    int idx = blockIdx.x;
    int c = idx % NC, bh = idx / NC;
    int b = bh / H_, h = bh % H_;
    int m0 = b * T_ + c * C_;
    int col = h * DH;
    int tid = threadIdx.x;

#pragma unroll
    for (int r = 0; r < 4; r++) {
        int e = tid + r * 256;
        int t = e >> 4; int d4 = (e & 15) * 4;
        float4 va = *reinterpret_cast<const float4*>(&g_a[(size_t)(m0 + t) * DI + col + d4]);
        *reinterpret_cast<float4*>(&sA[t * SROW + d4]) = va;
    }
    __syncthreads();
    if (tid < 64) {
        float g = 1.0f;
        for (int t = 0; t < 64; t++) { g *= sA[t * SROW + tid]; sA[t * SROW + tid] = g; }
    }
    __syncthreads();
#pragma unroll
    for (int r = 0; r < 4; r++) {
        int e = tid + r * 256;
        int t = e >> 4; int d4 = (e & 15) * 4;
        float4 vq = *reinterpret_cast<const float4*>(&g_q[(size_t)(m0 + t) * DI + col + d4]);
        float4 gg = *reinterpret_cast<const float4*>(&sA[t * SROW + d4]);
        vq.x *= gg.x; vq.y *= gg.y; vq.z *= gg.z; vq.w *= gg.w;
        *reinterpret_cast<float4*>(&sQ[t * SROW + d4]) = vq;
        *reinterpret_cast<float4*>(&g_q[(size_t)(m0 + t) * DI + col + d4]) = vq;
    }
    {
        int w = tid >> 5, l = tid & 31;
#pragma unroll
        for (int rr = 0; rr < 8; rr++) {
            int t = w * 8 + rr;
            float x0 = g_k[(size_t)(m0 + t) * DI + col + l];
            float x1 = g_k[(size_t)(m0 + t) * DI + col + l + 32];
            float s = x0 * x0 + x1 * x1;
#pragma unroll
            for (int o = 16; o; o >>= 1) s += __shfl_xor_sync(0xFFFFFFFFu, s, o);
            float inv = 1.0f / fmaxf(sqrtf(s), 1e-12f);
            sK[t * SROW + l]      = x0 * inv / sA[t * SROW + l];
            sK[t * SROW + l + 32] = x1 * inv / sA[t * SROW + l + 32];
        }
    }
#pragma unroll
    for (int r = 0; r < 4; r++) {
        int e = tid + r * 256;
        int t = e >> 4; int d4 = (e & 15) * 4;
        float4 vv = *reinterpret_cast<const float4*>(&g_v[(size_t)(m0 + t) * DI + col + d4]);
        *reinterpret_cast<float4*>(&sV[t * SROW + d4]) = vv;
    }
    if (tid < 64) g_D[(size_t)idx * 64 + tid] = sA[63 * SROW + tid];
    __syncthreads();

    int ty = tid >> 4, tx = tid & 15;
    int r0 = ty * 4, c0 = tx * 4;
    // U[j][i] = sum_s K~[s][j] V[s][i]
    {
        float acc[4][4];
#pragma unroll
        for (int a = 0; a < 4; a++)
#pragma unroll
            for (int bb2 = 0; bb2 < 4; bb2++) acc[a][bb2] = 0.f;
        for (int s = 0; s < 64; s++) {
            float4 kk = *reinterpret_cast<const float4*>(&sK[s * SROW + r0]);
            float4 vv = *reinterpret_cast<const float4*>(&sV[s * SROW + c0]);
            float ka[4] = {kk.x, kk.y, kk.z, kk.w};
            float vb[4] = {vv.x, vv.y, vv.z, vv.w};
#pragma unroll
            for (int a = 0; a < 4; a++)
#pragma unroll
                for (int bb2 = 0; bb2 < 4; bb2++) acc[a][bb2] += ka[a] * vb[bb2];
        }
#pragma unroll
        for (int a = 0; a < 4; a++) {
            float4 o4 = make_float4(acc[a][0], acc[a][1], acc[a][2], acc[a][3]);
            *reinterpret_cast<float4*>(&g_U[(size_t)idx * 4096 + (r0 + a) * 64 + c0]) = o4;
        }
    }
    // P[t][s] = sum_j Q~[t][j] K~[s][j] (float4 over j)
    {
        float acc[4][4];
#pragma unroll
        for (int a = 0; a < 4; a++)
#pragma unroll
            for (int bb2 = 0; bb2 < 4; bb2++) acc[a][bb2] = 0.f;
        for (int j = 0; j < 64; j += 4) {
            float4 qa4[4], kb4[4];
#pragma unroll
            for (int a = 0; a < 4; a++)
                qa4[a] = *reinterpret_cast<const float4*>(&sQ[(r0 + a) * SROW + j]);
#pragma unroll
            for (int bb2 = 0; bb2 < 4; bb2++)
                kb4[bb2] = *reinterpret_cast<const float4*>(&sK[(c0 + bb2) * SROW + j]);
#pragma unroll
            for (int a = 0; a < 4; a++)
#pragma unroll
                for (int bb2 = 0; bb2 < 4; bb2++) {
                    acc[a][bb2] += qa4[a].x * kb4[bb2].x;
                    acc[a][bb2] += qa4[a].y * kb4[bb2].y;
                    acc[a][bb2] += qa4[a].z * kb4[bb2].z;
                    acc[a][bb2] += qa4[a].w * kb4[bb2].w;
                }
        }
#pragma unroll
        for (int a = 0; a < 4; a++) {
#pragma unroll
            for (int bb2 = 0; bb2 < 4; bb2++)
                if (c0 + bb2 > r0 + a) acc[a][bb2] = 0.f;
            float4 o4 = make_float4(acc[a][0], acc[a][1], acc[a][2], acc[a][3]);
            *reinterpret_cast<float4*>(&sA[(r0 + a) * SROW + c0]) = o4;
        }
    }
    __syncthreads();
    // O_intra[t][i] = sum_s P[t][s] V[s][i] (float4 over s for P)
    {
        float acc[4][4];
#pragma unroll
        for (int a = 0; a < 4; a++)
#pragma unroll
            for (int bb2 = 0; bb2 < 4; bb2++) acc[a][bb2] = 0.f;
        for (int s = 0; s < 64; s += 4) {
            float4 pa4[4], vb4[4];
#pragma unroll
            for (int a = 0; a < 4; a++)
                pa4[a] = *reinterpret_cast<const float4*>(&sA[(r0 + a) * SROW + s]);
#pragma unroll
            for (int si = 0; si < 4; si++)
                vb4[si] = *reinterpret_cast<const float4*>(&sV[(s + si) * SROW + c0]);
#pragma unroll
            for (int a = 0; a < 4; a++) {
                acc[a][0] += pa4[a].x * vb4[0].x; acc[a][1] += pa4[a].x * vb4[0].y;
                acc[a][2] += pa4[a].x * vb4[0].z; acc[a][3] += pa4[a].x * vb4[0].w;
                acc[a][0] += pa4[a].y * vb4[1].x; acc[a][1] += pa4[a].y * vb4[1].y;
                acc[a][2] += pa4[a].y * vb4[1].z; acc[a][3] += pa4[a].y * vb4[1].w;
                acc[a][0] += pa4[a].z * vb4[2].x; acc[a][1] += pa4[a].z * vb4[2].y;
                acc[a][2] += pa4[a].z * vb4[2].z; acc[a][3] += pa4[a].z * vb4[2].w;
                acc[a][0] += pa4[a].w * vb4[3].x; acc[a][1] += pa4[a].w * vb4[3].y;
                acc[a][2] += pa4[a].w * vb4[3].z; acc[a][3] += pa4[a].w * vb4[3].w;
            }
        }
#pragma unroll
        for (int a = 0; a < 4; a++) {
            float4 o4 = make_float4(acc[a][0], acc[a][1], acc[a][2], acc[a][3]);
            *reinterpret_cast<float4*>(&g_o[(size_t)(m0 + r0 + a) * DI + col + c0]) = o4;
        }
    }
}

// ---------------------------------------------------------------------------
// Pass B: scan over chunks. grid (32, 8), 256 thr; float2/thread, MLP-8
// register ring prefetch.
// ---------------------------------------------------------------------------
__global__ void __launch_bounds__(256) rec_state() {
    int bh = blockIdx.x;
    int seg = blockIdx.y;
    int tid = threadIdx.x;
    int idx = seg * 512 + tid * 2;
    int j = idx >> 6;
    size_t base0 = (size_t)(bh * NC) * 4096 + idx;
    size_t dbase = (size_t)(bh * NC) * 64 + j;
    float2 S = make_float2(0.f, 0.f);
    float2 ub[8];
    float db[8];
#pragma unroll
    for (int i = 0; i < 8; i++) {
        ub[i] = *reinterpret_cast<const float2*>(&g_U[base0 + (size_t)i * 4096]);
        db[i] = g_D[dbase + (size_t)i * 64];
    }
    for (int c = 0; c < NC; c += 8) {
#pragma unroll
        for (int q = 0; q < 8; q++) {
            int cc = c + q;
            *reinterpret_cast<float2*>(&g_S[base0 + (size_t)cc * 4096]) = S;
            float2 uc = ub[q];
            float dc = db[q];
            if (cc + 8 < NC) {
                ub[q] = *reinterpret_cast<const float2*>(&g_U[base0 + (size_t)(cc + 8) * 4096]);
                db[q] = g_D[dbase + (size_t)(cc + 8) * 64];
            }
            S.x = dc * (S.x + uc.x);
            S.y = dc * (S.y + uc.y);
        }
    }
}

// ---------------------------------------------------------------------------
// Pass C: O = g_o (intra) + q~ @ S_in, written as fp16 hi only.
// ---------------------------------------------------------------------------
__global__ void __launch_bounds__(256) rec_inter() {
    __shared__ float sQ[64 * SROW];
    __shared__ float sS[64 * SROW];
    int idx = blockIdx.x;
    int c = idx % NC, bh = idx / NC;
    int b = bh / H_, h = bh % H_;
    int m0 = b * T_ + c * C_;
    int col = h * DH;
    int tid = threadIdx.x;
#pragma unroll
    for (int r = 0; r < 4; r++) {
        int e = tid + r * 256;
        int t = e >> 4; int d4 = (e & 15) * 4;
        *reinterpret_cast<float4*>(&sQ[t * SROW + d4]) =
            *reinterpret_cast<const float4*>(&g_q[(size_t)(m0 + t) * DI + col + d4]);
        *reinterpret_cast<float4*>(&sS[t * SROW + d4]) =
            *reinterpret_cast<const float4*>(&g_S[(size_t)idx * 4096 + t * 64 + d4]);
    }
    __syncthreads();
    int ty = tid >> 4, tx = tid & 15;
    int r0 = ty * 4, c0 = tx * 4;
    float acc[4][4];
#pragma unroll
    for (int a = 0; a < 4; a++)
#pragma unroll
        for (int bb2 = 0; bb2 < 4; bb2++) acc[a][bb2] = 0.f;
    for (int j = 0; j < 64; j += 4) {
        float4 qa4[4], sv4[4];
#pragma unroll
        for (int a = 0; a < 4; a++)
            qa4[a] = *reinterpret_cast<const float4*>(&sQ[(r0 + a) * SROW + j]);
#pragma unroll
        for (int ji = 0; ji < 4; ji++)
            sv4[ji] = *reinterpret_cast<const float4*>(&sS[(j + ji) * SROW + c0]);
#pragma unroll
        for (int a = 0; a < 4; a++) {
            acc[a][0] += qa4[a].x * sv4[0].x; acc[a][1] += qa4[a].x * sv4[0].y;
            acc[a][2] += qa4[a].x * sv4[0].z; acc[a][3] += qa4[a].x * sv4[0].w;
            acc[a][0] += qa4[a].y * sv4[1].x; acc[a][1] += qa4[a].y * sv4[1].y;
            acc[a][2] += qa4[a].y * sv4[1].z; acc[a][3] += qa4[a].y * sv4[1].w;
            acc[a][0] += qa4[a].z * sv4[2].x; acc[a][1] += qa4[a].z * sv4[2].y;
            acc[a][2] += qa4[a].z * sv4[2].z; acc[a][3] += qa4[a].z * sv4[2].w;
            acc[a][0] += qa4[a].w * sv4[3].x; acc[a][1] += qa4[a].w * sv4[3].y;
            acc[a][2] += qa4[a].w * sv4[3].z; acc[a][3] += qa4[a].w * sv4[3].w;
        }
    }
#pragma unroll
    for (int a = 0; a < 4; a++) {
        size_t off = (size_t)(m0 + r0 + a) * DI + col + c0;
        float4 cur = *reinterpret_cast<const float4*>(&g_o[off]);
        hi4_store(cur.x + acc[a][0], cur.y + acc[a][1],
                  cur.z + acc[a][2], cur.w + acc[a][3], g_oh, off);
    }
}

// ---------------------------------------------------------------------------
extern "C" void kernel_launch(void* const* d_in, const int* in_sizes, int n_in,
                              void* d_out, int out_size) {
    const float* x     = (const float*)d_in[0];
    const float* Wq    = (const float*)d_in[1];
    const float* Wk    = (const float*)d_in[2];
    const float* Wv    = (const float*)d_in[3];
    const float* Wa    = (const float*)d_in[4];
    const float* ba    = (const float*)d_in[5];
    const float* Wo    = (const float*)d_in[6];
    const float* gamma = (const float*)d_in[7];
    const float* beta  = (const float*)d_in[8];
    float* out = (float*)d_out;

    const int smemA = 4 * 64 * SROW * sizeof(float);
    cudaFuncSetAttribute(rec_intra, cudaFuncAttributeMaxDynamicSharedMemorySize, smemA);
    cudaFuncSetAttribute(proj_hmma, cudaFuncAttributeMaxDynamicSharedMemorySize, GEMM_SMEM);
    cudaFuncSetAttribute(out_hmma, cudaFuncAttributeMaxDynamicSharedMemorySize, GEMM_SMEM);

    prep_kernel<<<M_ + 5 * 512, 256>>>(x, gamma, beta, Wq, Wk, Wv, Wa, Wo);
    proj_hmma<<<dim3(16, 128), 256, GEMM_SMEM>>>(ba);
    rec_intra<<<NCHUNK, 256, smemA>>>();
    rec_state<<<dim3(32, 8), 256>>>();
    rec_inter<<<NCHUNK, 256>>>();
    out_hmma<<<dim3(8, 128), 256, GEMM_SMEM>>>(x, out);
}